// round 8
// baseline (speedup 1.0000x reference)
#include <cuda_runtime.h>
#include <cuda_bf16.h>
#include <cuda_fp16.h>
#include <math.h>

#define T_ 16
#define B_ 1024
#define F_DIM 512
#define H_ 128
#define L_ 512
#define C_ 100
#define FSPLIT 2
#define KSPLIT (T_ * FSPLIT)

// Scratch (static device globals -- no allocation allowed)
__device__ __nv_bfloat16 g_h[(size_t)T_ * B_ * H_];       // 4 MB
__device__ __nv_bfloat16 g_mu[(size_t)T_ * B_ * L_];      // 16 MB
__device__ unsigned g_lp[(size_t)T_ * (L_ / 2) * 128];    // 2 MB  packed leafp pairs
__device__ float g_part[(size_t)KSPLIT * B_ * C_];        // 13 MB
__device__ unsigned g_pf[(size_t)B_ * (F_DIM / 2)];       // 1 MB  packed feat pairs
__device__ unsigned g_pw1[(size_t)T_ * (F_DIM / 2) * H_]; // 2 MB  packed W1 pairs
__device__ unsigned g_pw2[(size_t)T_ * (H_ / 2) * L_];    // 2 MB  packed W2 pairs

__device__ __forceinline__ unsigned pkf(float lo, float hi) {
    __nv_bfloat162 h = __floats2bfloat162_rn(lo, hi);
    return *reinterpret_cast<unsigned*>(&h);
}

__device__ __forceinline__ void mma_bf16(float* d, const unsigned* a, const unsigned* b) {
    asm volatile(
        "mma.sync.aligned.m16n8k16.row.col.f32.bf16.bf16.f32 "
        "{%0,%1,%2,%3}, {%4,%5,%6,%7}, {%8,%9}, {%0,%1,%2,%3};\n"
        : "+f"(d[0]), "+f"(d[1]), "+f"(d[2]), "+f"(d[3])
        : "r"(a[0]), "r"(a[1]), "r"(a[2]), "r"(a[3]), "r"(b[0]), "r"(b[1]));
}

__device__ __forceinline__ void cp16(void* s, const void* g) {
    unsigned sa = (unsigned)__cvta_generic_to_shared(s);
    asm volatile("cp.async.ca.shared.global [%0], [%1], 16;\n" :: "r"(sa), "l"(g));
}
#define CP_COMMIT() asm volatile("cp.async.commit_group;\n")
#define CP_WAIT1()  asm volatile("cp.async.wait_group 1;\n")
#define CP_WAIT0()  asm volatile("cp.async.wait_group 0;\n")

// ---------------------------------------------------------------------------
// Pack feat / W1 / W2 into bf16x2 (pairs over k) MMA-ready layouts.
// ---------------------------------------------------------------------------
__global__ __launch_bounds__(256) void pack_inputs(const float* __restrict__ feat,
                                                   const float* __restrict__ W1,
                                                   const float* __restrict__ W2) {
    const int i = blockIdx.x * 256 + threadIdx.x;
    if (blockIdx.y == 0) {
        if (i < B_ * (F_DIM / 2)) {
            float2 v = *reinterpret_cast<const float2*>(&feat[(size_t)i * 2]);
            g_pf[i] = pkf(v.x, v.y);
        }
    } else if (blockIdx.y == 1) {
        int t = i >> 15, rem = i & 32767, f2 = rem >> 7, n = rem & 127;
        const float* base = W1 + ((size_t)t * F_DIM + 2 * f2) * H_ + n;
        g_pw1[i] = pkf(base[0], base[H_]);
    } else {
        int t = i >> 15, h2 = (i >> 9) & 63, l = i & 511;
        const float* base = W2 + ((size_t)t * H_ + 2 * h2) * L_ + l;
        g_pw2[i] = pkf(base[0], base[L_]);
    }
}

// ---------------------------------------------------------------------------
// Stage 1: h = relu(feat @ W1 + b1). 64x128 tile, BK=32, cp.async 2-stage.
// grid (B/64, 1, T) = 256 CTAs, 256 threads.
// ---------------------------------------------------------------------------
__global__ __launch_bounds__(256) void gemm1_bf16(const float* __restrict__ b1) {
    __shared__ unsigned As[2][64 * 20];
    __shared__ unsigned Bs[2][16 * 132];

    const int tid = threadIdx.x;
    const int wid = tid >> 5, lane = tid & 31;
    const int warp_m = wid >> 2, warp_n = wid & 3;
    const int lq = lane >> 2, lr = lane & 3;
    const int t = blockIdx.z;
    const int b0 = blockIdx.x * 64;

    const unsigned* pf = g_pf + (size_t)b0 * (F_DIM / 2);
    const unsigned* pw = g_pw1 + (size_t)t * (F_DIM / 2) * H_;
    const float* bb = b1 + (size_t)t * H_;

    float acc[2][4][4];
#pragma unroll
    for (int i = 0; i < 2; i++)
#pragma unroll
        for (int j = 0; j < 4; j++)
#pragma unroll
            for (int q = 0; q < 4; q++) acc[i][j][q] = 0.0f;

    auto issue = [&](int kt, int buf) {
        const int kp0 = kt * 16;
        {
            int r = tid >> 2, q = tid & 3;
            cp16(&As[buf][r * 20 + q * 4], &pf[(size_t)r * (F_DIM / 2) + kp0 + q * 4]);
        }
#pragma unroll
        for (int i = 0; i < 2; i++) {
            int e = tid + i * 256;
            int kp = e >> 5, c4 = e & 31;
            cp16(&Bs[buf][kp * 132 + c4 * 4], &pw[(size_t)(kp0 + kp) * H_ + c4 * 4]);
        }
        CP_COMMIT();
    };

    issue(0, 0);
#pragma unroll 1
    for (int kt = 0; kt < 16; kt++) {
        const int buf = kt & 1;
        if (kt < 15) { issue(kt + 1, buf ^ 1); CP_WAIT1(); } else { CP_WAIT0(); }
        __syncthreads();

#pragma unroll
        for (int kh = 0; kh < 2; kh++) {
            const int kb = kh * 8;
            unsigned afr[2][4], bfr[4][2];
#pragma unroll
            for (int im = 0; im < 2; im++) {
                int r = warp_m * 32 + im * 16;
                afr[im][0] = As[buf][(r + lq) * 20 + kb + lr];
                afr[im][1] = As[buf][(r + 8 + lq) * 20 + kb + lr];
                afr[im][2] = As[buf][(r + lq) * 20 + kb + 4 + lr];
                afr[im][3] = As[buf][(r + 8 + lq) * 20 + kb + 4 + lr];
            }
#pragma unroll
            for (int jn = 0; jn < 4; jn++) {
                int c = warp_n * 32 + jn * 8 + lq;
                bfr[jn][0] = Bs[buf][(kb + lr) * 132 + c];
                bfr[jn][1] = Bs[buf][(kb + 4 + lr) * 132 + c];
            }
#pragma unroll
            for (int im = 0; im < 2; im++)
#pragma unroll
                for (int jn = 0; jn < 4; jn++) mma_bf16(acc[im][jn], afr[im], bfr[jn]);
        }
        __syncthreads();
    }

    unsigned* gh = reinterpret_cast<unsigned*>(g_h);
#pragma unroll
    for (int im = 0; im < 2; im++) {
#pragma unroll
        for (int half = 0; half < 2; half++) {
            int r = warp_m * 32 + im * 16 + half * 8 + lq;
#pragma unroll
            for (int jn = 0; jn < 4; jn++) {
                int c = warp_n * 32 + jn * 8 + lr * 2;
                float x0 = fmaxf(acc[im][jn][half * 2 + 0] + bb[c], 0.0f);
                float x1 = fmaxf(acc[im][jn][half * 2 + 1] + bb[c + 1], 0.0f);
                gh[((size_t)t * B_ + b0 + r) * (H_ / 2) + (c >> 1)] = pkf(x0, x1);
            }
        }
    }
}

// ---------------------------------------------------------------------------
// Stage 2 fused: p = sigmoid(h @ W2 + b2) (staged fp16 smem) then mu routing
// products (16-leaf register subtrees). 512 threads (16 warps, 4x4 layout)
// on a 64-row tile -> 32 warps/SM at 2 CTAs/SM. grid (B/64, T) = 256 CTAs.
// ---------------------------------------------------------------------------
#define SM2_HA (64 * 68)
#define SM2_BS (16 * 132)
#define SM2_BYTES ((SM2_HA + 2 * SM2_BS) * 4 + 64 * 520 * 2)

__global__ __launch_bounds__(512, 2) void stage2_fused(const float* __restrict__ b2) {
    extern __shared__ unsigned smemu[];
    unsigned* hA = smemu;                                   // [64][68]
    unsigned* Bs0 = smemu + SM2_HA;                         // [2][16*132]
    __half* ph = reinterpret_cast<__half*>(smemu + SM2_HA + 2 * SM2_BS);  // [64][520]

    const int tid = threadIdx.x;
    const int wid = tid >> 5, lane = tid & 31;
    const int warp_m = wid >> 2, warp_n = wid & 3;   // 4x4 warps, 16x32 warp tiles
    const int lq = lane >> 2, lr = lane & 3;
    const int t = blockIdx.y;
    const int b0 = blockIdx.x * 64;

    // h tile resident: 64 x 64 u32 = 1024 uint4, 2 per thread.
    const unsigned* hsrc = reinterpret_cast<const unsigned*>(g_h) + ((size_t)t * B_ + b0) * (H_ / 2);
#pragma unroll
    for (int i = 0; i < 2; i++) {
        int e = tid + i * 512;
        int r = e >> 4, q = e & 15;
        cp16(&hA[r * 68 + q * 4], &hsrc[(size_t)r * 64 + q * 4]);
    }
    CP_COMMIT();

    const unsigned* pw = g_pw2 + (size_t)t * (H_ / 2) * L_;
    const float* bbt = b2 + (size_t)t * L_;

    auto issue = [&](int j, int buf) {
        const int chunk = j >> 2, k0s = j & 3;
        const unsigned* src = pw + (size_t)(k0s * 16) * L_ + chunk * 128;
        // 16 x 128 u32 = 512 uint4, 1 per thread
        int kp = tid >> 5, c4 = tid & 31;
        cp16(&Bs0[buf * SM2_BS + kp * 132 + c4 * 4], &src[(size_t)kp * L_ + c4 * 4]);
        CP_COMMIT();
    };

    issue(0, 0);

    float acc[4][4];
#pragma unroll 1
    for (int j = 0; j < 16; j++) {
        const int chunk = j >> 2, k0s = j & 3, buf = j & 1;
        if (k0s == 0) {
#pragma unroll
            for (int jj = 0; jj < 4; jj++)
#pragma unroll
                for (int q = 0; q < 4; q++) acc[jj][q] = 0.0f;
        }
        if (j < 15) { issue(j + 1, buf ^ 1); CP_WAIT1(); } else { CP_WAIT0(); }
        __syncthreads();

        const unsigned* Bs = Bs0 + buf * SM2_BS;
#pragma unroll
        for (int kh = 0; kh < 2; kh++) {
            const int kbG = k0s * 16 + kh * 8;
            const int kbB = kh * 8;
            unsigned afr[4], bfr[4][2];
            {
                int r = warp_m * 16;
                afr[0] = hA[(r + lq) * 68 + kbG + lr];
                afr[1] = hA[(r + 8 + lq) * 68 + kbG + lr];
                afr[2] = hA[(r + lq) * 68 + kbG + 4 + lr];
                afr[3] = hA[(r + 8 + lq) * 68 + kbG + 4 + lr];
            }
#pragma unroll
            for (int jn = 0; jn < 4; jn++) {
                int c = warp_n * 32 + jn * 8 + lq;
                bfr[jn][0] = Bs[(kbB + lr) * 132 + c];
                bfr[jn][1] = Bs[(kbB + 4 + lr) * 132 + c];
            }
#pragma unroll
            for (int jn = 0; jn < 4; jn++) mma_bf16(acc[jn], afr, bfr[jn]);
        }

        if (k0s == 3) {
            const int n0c = chunk * 128;
#pragma unroll
            for (int half = 0; half < 2; half++) {
                int r = warp_m * 16 + half * 8 + lq;
#pragma unroll
                for (int jn = 0; jn < 4; jn++) {
                    int c = warp_n * 32 + jn * 8 + lr * 2;
                    float x0 = 1.0f / (1.0f + __expf(-(acc[jn][half * 2 + 0] + bbt[n0c + c])));
                    float x1 = 1.0f / (1.0f + __expf(-(acc[jn][half * 2 + 1] + bbt[n0c + c + 1])));
                    *reinterpret_cast<__half2*>(&ph[r * 520 + n0c + c]) = __floats2half2_rn(x0, x1);
                }
            }
        }
        __syncthreads();
    }

    // mu phase: 64 rows x 32 subtrees (16 leaves) = 2048 tasks, 4 per thread.
    unsigned* muout = reinterpret_cast<unsigned*>(g_mu) + ((size_t)t * B_ + b0) * (L_ / 2);
#pragma unroll 1
    for (int i = 0; i < 4; i++) {
        int task = i * 512 + tid;
        int row = task >> 5;
        int s = task & 31;
        int l0 = s << 4;
        const __half* sp = ph + row * 520;

        float pref = 1.0f;
#pragma unroll
        for (int d = 0; d < 5; d++) {
            int node = (1 << d) - 1 + (l0 >> (9 - d));
            float v = __half2float(sp[node]);
            pref *= ((l0 >> (8 - d)) & 1) ? (1.0f - v) : v;
        }

        float cur[16];
        cur[0] = pref;
#pragma unroll
        for (int d = 5; d <= 8; d++) {
            const int width = 1 << (d - 5);
            const int nbase = (1 << d) - 1 + (l0 >> (9 - d));
#pragma unroll
            for (int ii = width - 1; ii >= 0; ii--) {
                float v = __half2float(sp[nbase + ii]);
                float x = cur[ii];
                cur[2 * ii] = x * v;
                cur[2 * ii + 1] = x * (1.0f - v);
            }
        }

        unsigned w[8];
#pragma unroll
        for (int jj = 0; jj < 8; jj++) w[jj] = pkf(cur[2 * jj], cur[2 * jj + 1]);
        unsigned* dst = muout + (size_t)row * (L_ / 2) + s * 8;
        *reinterpret_cast<uint4*>(dst) = *reinterpret_cast<uint4*>(&w[0]);
        *reinterpret_cast<uint4*>(dst + 4) = *reinterpret_cast<uint4*>(&w[4]);
    }
}

// ---------------------------------------------------------------------------
// Leaf softmax -> packed layout g_lp[t][l/2][128] (bf16x2 over l, zero-pad).
// ---------------------------------------------------------------------------
__global__ __launch_bounds__(128) void leaf_softmax_pack(const float* __restrict__ pi) {
    const int row = blockIdx.x * 4 + (threadIdx.x >> 5);   // t*L + l
    const int lane = threadIdx.x & 31;
    const int t = row >> 9, l = row & (L_ - 1);
    const float* pr = pi + (size_t)row * C_;

    float v[4];
#pragma unroll
    for (int j = 0; j < 4; j++) {
        int c = lane + j * 32;
        v[j] = (c < C_) ? pr[c] : -1e30f;
    }
    float m = fmaxf(fmaxf(v[0], v[1]), fmaxf(v[2], v[3]));
#pragma unroll
    for (int o = 16; o; o >>= 1) m = fmaxf(m, __shfl_xor_sync(0xffffffffu, m, o));

    float e[4];
    float s = 0.0f;
#pragma unroll
    for (int j = 0; j < 4; j++) {
        int c = lane + j * 32;
        e[j] = (c < C_) ? __expf(v[j] - m) : 0.0f;
        s += e[j];
    }
#pragma unroll
    for (int o = 16; o; o >>= 1) s += __shfl_xor_sync(0xffffffffu, s, o);
    float inv = 1.0f / s;

    unsigned short* base = reinterpret_cast<unsigned short*>(g_lp);
    const size_t rowbase = ((size_t)t * (L_ / 2) + (l >> 1)) * 128;
#pragma unroll
    for (int j = 0; j < 4; j++) {
        int c = lane + j * 32;
        __nv_bfloat16 bv = __float2bfloat16((c < C_) ? e[j] * inv : 0.0f);
        base[(rowbase + c) * 2 + (l & 1)] = *reinterpret_cast<unsigned short*>(&bv);
    }
}

// ---------------------------------------------------------------------------
// Final contraction: part[t*2+ks] = mu[t][:, ks*256:+256] @ leafp chunk.
// 128x128 tile, K=256 per CTA, cp.async double-buffered. grid (8, T, 2).
// ---------------------------------------------------------------------------
__global__ __launch_bounds__(256) void final_bf16() {
    __shared__ unsigned As[2][128 * 20];
    __shared__ unsigned Bs[2][16 * 132];

    const int tid = threadIdx.x;
    const int wid = tid >> 5, lane = tid & 31;
    const int warp_m = wid >> 2, warp_n = wid & 3;
    const int lq = lane >> 2, lr = lane & 3;
    const int t = blockIdx.y;
    const int ks = blockIdx.z;
    const int b0 = blockIdx.x * 128;

    const unsigned* mu_u = reinterpret_cast<const unsigned*>(g_mu) + ((size_t)t * B_ + b0) * (L_ / 2);
    const unsigned* lpb = g_lp + (size_t)t * (L_ / 2) * 128;

    float acc[4][4][4];
#pragma unroll
    for (int i = 0; i < 4; i++)
#pragma unroll
        for (int j = 0; j < 4; j++)
#pragma unroll
            for (int q = 0; q < 4; q++) acc[i][j][q] = 0.0f;

    auto issue = [&](int kt, int buf) {
        const int kp0 = (ks * 256 + kt * 32) >> 1;
#pragma unroll
        for (int i = 0; i < 2; i++) {
            int e = tid + i * 256;
            int r = e >> 2, q = e & 3;
            cp16(&As[buf][r * 20 + q * 4], &mu_u[(size_t)r * (L_ / 2) + kp0 + q * 4]);
        }
#pragma unroll
        for (int i = 0; i < 2; i++) {
            int e = tid + i * 256;
            int kp = e >> 5, c4 = e & 31;
            cp16(&Bs[buf][kp * 132 + c4 * 4], &lpb[(size_t)(kp0 + kp) * 128 + c4 * 4]);
        }
        CP_COMMIT();
    };

    issue(0, 0);
#pragma unroll 1
    for (int kt = 0; kt < 8; kt++) {
        const int buf = kt & 1;
        if (kt < 7) { issue(kt + 1, buf ^ 1); CP_WAIT1(); } else { CP_WAIT0(); }
        __syncthreads();

#pragma unroll
        for (int kh = 0; kh < 2; kh++) {
            const int kb = kh * 8;
            unsigned bfr[4][2];
#pragma unroll
            for (int jn = 0; jn < 4; jn++) {
                int c = warp_n * 32 + jn * 8 + lq;
                bfr[jn][0] = Bs[buf][(kb + lr) * 132 + c];
                bfr[jn][1] = Bs[buf][(kb + 4 + lr) * 132 + c];
            }
#pragma unroll
            for (int im = 0; im < 4; im++) {
                int r = warp_m * 64 + im * 16;
                unsigned afr[4];
                afr[0] = As[buf][(r + lq) * 20 + kb + lr];
                afr[1] = As[buf][(r + 8 + lq) * 20 + kb + lr];
                afr[2] = As[buf][(r + lq) * 20 + kb + 4 + lr];
                afr[3] = As[buf][(r + 8 + lq) * 20 + kb + 4 + lr];
#pragma unroll
                for (int jn = 0; jn < 4; jn++) mma_bf16(acc[im][jn], afr, bfr[jn]);
            }
        }
        __syncthreads();
    }

    float* pb = g_part + (size_t)(t * FSPLIT + ks) * B_ * C_;
#pragma unroll
    for (int im = 0; im < 4; im++) {
#pragma unroll
        for (int half = 0; half < 2; half++) {
            int r = warp_m * 64 + im * 16 + half * 8 + lq;
#pragma unroll
            for (int jn = 0; jn < 4; jn++) {
                int c = warp_n * 32 + jn * 8 + lr * 2;
                if (c >= C_) continue;
                *reinterpret_cast<float2*>(&pb[(size_t)(b0 + r) * C_ + c]) =
                    make_float2(acc[im][jn][half * 2 + 0], acc[im][jn][half * 2 + 1]);
            }
        }
    }
}

// ---------------------------------------------------------------------------
// Deterministic reduction over KSPLIT partials + final log
// ---------------------------------------------------------------------------
__global__ __launch_bounds__(256) void reduce_log_kernel(float* __restrict__ out) {
    const int i = blockIdx.x * 256 + threadIdx.x;
    float s = 0.0f;
#pragma unroll
    for (int ks = 0; ks < KSPLIT; ks++) s += g_part[(size_t)ks * B_ * C_ + i];
    out[i] = logf(s * (1.0f / (float)(L_ * T_)));
}

extern "C" void kernel_launch(void* const* d_in, const int* in_sizes, int n_in,
                              void* d_out, int out_size) {
    const float* feat = (const float*)d_in[0];
    const float* W1 = (const float*)d_in[1];
    const float* b1 = (const float*)d_in[2];
    const float* W2 = (const float*)d_in[3];
    const float* b2 = (const float*)d_in[4];
    const float* pi = (const float*)d_in[5];
    float* out = (float*)d_out;

    cudaFuncSetAttribute(stage2_fused, cudaFuncAttributeMaxDynamicSharedMemorySize, SM2_BYTES);

    pack_inputs<<<dim3(2048, 3), 256>>>(feat, W1, W2);
    leaf_softmax_pack<<<(T_ * L_) / 4, 128>>>(pi);
    gemm1_bf16<<<dim3(B_ / 64, 1, T_), 256>>>(b1);
    stage2_fused<<<dim3(B_ / 64, T_), 512, SM2_BYTES>>>(b2);
    final_bf16<<<dim3(B_ / 128, T_, FSPLIT), 256>>>();
    reduce_log_kernel<<<(B_ * C_) / 256, 256>>>(out);
}

// round 9
// speedup vs baseline: 1.0462x; 1.0462x over previous
#include <cuda_runtime.h>
#include <cuda_bf16.h>
#include <cuda_fp16.h>
#include <math.h>

#define T_ 16
#define B_ 1024
#define F_DIM 512
#define H_ 128
#define L_ 512
#define C_ 100
#define FSPLIT 2
#define KSPLIT (T_ * FSPLIT)

// Scratch (static device globals -- no allocation allowed)
__device__ __nv_bfloat16 g_h[(size_t)T_ * B_ * H_];       // 4 MB
__device__ __nv_bfloat16 g_mu[(size_t)T_ * B_ * L_];      // 16 MB
__device__ unsigned g_lp[(size_t)T_ * (L_ / 2) * 128];    // 2 MB  packed leafp pairs
__device__ float g_part[(size_t)KSPLIT * B_ * C_];        // 13 MB
__device__ unsigned g_pf[(size_t)B_ * (F_DIM / 2)];       // 1 MB  packed feat pairs
__device__ unsigned g_pw1[(size_t)T_ * (F_DIM / 2) * H_]; // 2 MB  packed W1 pairs
__device__ unsigned g_pw2[(size_t)T_ * (H_ / 2) * L_];    // 2 MB  packed W2 pairs

__device__ __forceinline__ unsigned pkf(float lo, float hi) {
    __nv_bfloat162 h = __floats2bfloat162_rn(lo, hi);
    return *reinterpret_cast<unsigned*>(&h);
}

__device__ __forceinline__ void mma_bf16(float* d, const unsigned* a, const unsigned* b) {
    asm volatile(
        "mma.sync.aligned.m16n8k16.row.col.f32.bf16.bf16.f32 "
        "{%0,%1,%2,%3}, {%4,%5,%6,%7}, {%8,%9}, {%0,%1,%2,%3};\n"
        : "+f"(d[0]), "+f"(d[1]), "+f"(d[2]), "+f"(d[3])
        : "r"(a[0]), "r"(a[1]), "r"(a[2]), "r"(a[3]), "r"(b[0]), "r"(b[1]));
}

__device__ __forceinline__ void cp16(void* s, const void* g) {
    unsigned sa = (unsigned)__cvta_generic_to_shared(s);
    asm volatile("cp.async.ca.shared.global [%0], [%1], 16;\n" :: "r"(sa), "l"(g));
}
#define CP_COMMIT() asm volatile("cp.async.commit_group;\n")
#define CP_WAIT1()  asm volatile("cp.async.wait_group 1;\n")
#define CP_WAIT0()  asm volatile("cp.async.wait_group 0;\n")

// ---------------------------------------------------------------------------
// Pack feat / W1 / W2 into bf16x2 (pairs over k) MMA-ready layouts.
// ---------------------------------------------------------------------------
__global__ __launch_bounds__(256) void pack_inputs(const float* __restrict__ feat,
                                                   const float* __restrict__ W1,
                                                   const float* __restrict__ W2) {
    const int i = blockIdx.x * 256 + threadIdx.x;
    if (blockIdx.y == 0) {
        if (i < B_ * (F_DIM / 2)) {
            float2 v = *reinterpret_cast<const float2*>(&feat[(size_t)i * 2]);
            g_pf[i] = pkf(v.x, v.y);
        }
    } else if (blockIdx.y == 1) {
        int t = i >> 15, rem = i & 32767, f2 = rem >> 7, n = rem & 127;
        const float* base = W1 + ((size_t)t * F_DIM + 2 * f2) * H_ + n;
        g_pw1[i] = pkf(base[0], base[H_]);
    } else {
        int t = i >> 15, h2 = (i >> 9) & 63, l = i & 511;
        const float* base = W2 + ((size_t)t * H_ + 2 * h2) * L_ + l;
        g_pw2[i] = pkf(base[0], base[L_]);
    }
}

// ---------------------------------------------------------------------------
// Stage 1: h = relu(feat @ W1 + b1). 64x128 tile, BK=32, cp.async 2-stage.
// grid (B/64, 1, T) = 256 CTAs, 256 threads.
// ---------------------------------------------------------------------------
__global__ __launch_bounds__(256) void gemm1_bf16(const float* __restrict__ b1) {
    __shared__ unsigned As[2][64 * 20];
    __shared__ unsigned Bs[2][16 * 132];

    const int tid = threadIdx.x;
    const int wid = tid >> 5, lane = tid & 31;
    const int warp_m = wid >> 2, warp_n = wid & 3;
    const int lq = lane >> 2, lr = lane & 3;
    const int t = blockIdx.z;
    const int b0 = blockIdx.x * 64;

    const unsigned* pf = g_pf + (size_t)b0 * (F_DIM / 2);
    const unsigned* pw = g_pw1 + (size_t)t * (F_DIM / 2) * H_;
    const float* bb = b1 + (size_t)t * H_;

    float acc[2][4][4];
#pragma unroll
    for (int i = 0; i < 2; i++)
#pragma unroll
        for (int j = 0; j < 4; j++)
#pragma unroll
            for (int q = 0; q < 4; q++) acc[i][j][q] = 0.0f;

    auto issue = [&](int kt, int buf) {
        const int kp0 = kt * 16;
        {
            int r = tid >> 2, q = tid & 3;
            cp16(&As[buf][r * 20 + q * 4], &pf[(size_t)r * (F_DIM / 2) + kp0 + q * 4]);
        }
#pragma unroll
        for (int i = 0; i < 2; i++) {
            int e = tid + i * 256;
            int kp = e >> 5, c4 = e & 31;
            cp16(&Bs[buf][kp * 132 + c4 * 4], &pw[(size_t)(kp0 + kp) * H_ + c4 * 4]);
        }
        CP_COMMIT();
    };

    issue(0, 0);
#pragma unroll 1
    for (int kt = 0; kt < 16; kt++) {
        const int buf = kt & 1;
        if (kt < 15) { issue(kt + 1, buf ^ 1); CP_WAIT1(); } else { CP_WAIT0(); }
        __syncthreads();

#pragma unroll
        for (int kh = 0; kh < 2; kh++) {
            const int kb = kh * 8;
            unsigned afr[2][4], bfr[4][2];
#pragma unroll
            for (int im = 0; im < 2; im++) {
                int r = warp_m * 32 + im * 16;
                afr[im][0] = As[buf][(r + lq) * 20 + kb + lr];
                afr[im][1] = As[buf][(r + 8 + lq) * 20 + kb + lr];
                afr[im][2] = As[buf][(r + lq) * 20 + kb + 4 + lr];
                afr[im][3] = As[buf][(r + 8 + lq) * 20 + kb + 4 + lr];
            }
#pragma unroll
            for (int jn = 0; jn < 4; jn++) {
                int c = warp_n * 32 + jn * 8 + lq;
                bfr[jn][0] = Bs[buf][(kb + lr) * 132 + c];
                bfr[jn][1] = Bs[buf][(kb + 4 + lr) * 132 + c];
            }
#pragma unroll
            for (int im = 0; im < 2; im++)
#pragma unroll
                for (int jn = 0; jn < 4; jn++) mma_bf16(acc[im][jn], afr[im], bfr[jn]);
        }
        __syncthreads();
    }

    unsigned* gh = reinterpret_cast<unsigned*>(g_h);
#pragma unroll
    for (int im = 0; im < 2; im++) {
#pragma unroll
        for (int half = 0; half < 2; half++) {
            int r = warp_m * 32 + im * 16 + half * 8 + lq;
#pragma unroll
            for (int jn = 0; jn < 4; jn++) {
                int c = warp_n * 32 + jn * 8 + lr * 2;
                float x0 = fmaxf(acc[im][jn][half * 2 + 0] + bb[c], 0.0f);
                float x1 = fmaxf(acc[im][jn][half * 2 + 1] + bb[c + 1], 0.0f);
                gh[((size_t)t * B_ + b0 + r) * (H_ / 2) + (c >> 1)] = pkf(x0, x1);
            }
        }
    }
}

// ---------------------------------------------------------------------------
// Stage 2 fused: p = sigmoid(h @ W2 + b2) staged in fp16 smem with SHIFTED
// layout (node n -> slot n+1, so depth d starts at slot 2^d), then mu routing
// products with VECTORIZED tree reads (LDS.32/.64/.128, conflict-free).
// grid (B/64, T) = 256 CTAs, 256 threads.
// ---------------------------------------------------------------------------
#define SM2_HA (64 * 68)
#define SM2_BS (16 * 132)
#define PH_STRIDE 520
#define SM2_BYTES ((SM2_HA + 2 * SM2_BS) * 4 + 64 * PH_STRIDE * 2)

__global__ __launch_bounds__(256) void stage2_fused(const float* __restrict__ b2) {
    extern __shared__ unsigned smemu[];
    unsigned* hA = smemu;                                   // [64][68]
    unsigned* Bs0 = smemu + SM2_HA;                         // [2][16*132]
    __half* ph = reinterpret_cast<__half*>(smemu + SM2_HA + 2 * SM2_BS);  // [64][520]

    const int tid = threadIdx.x;
    const int wid = tid >> 5, lane = tid & 31;
    const int warp_m = wid >> 2, warp_n = wid & 3;
    const int lq = lane >> 2, lr = lane & 3;
    const int t = blockIdx.y;
    const int b0 = blockIdx.x * 64;

    const unsigned* hsrc = reinterpret_cast<const unsigned*>(g_h) + ((size_t)t * B_ + b0) * (H_ / 2);
#pragma unroll
    for (int i = 0; i < 4; i++) {
        int e = tid + i * 256;
        int r = e >> 4, q = e & 15;
        cp16(&hA[r * 68 + q * 4], &hsrc[(size_t)r * 64 + q * 4]);
    }
    CP_COMMIT();

    const unsigned* pw = g_pw2 + (size_t)t * (H_ / 2) * L_;
    const float* bbt = b2 + (size_t)t * L_;

    auto issue = [&](int j, int buf) {
        const int chunk = j >> 2, k0s = j & 3;
        const unsigned* src = pw + (size_t)(k0s * 16) * L_ + chunk * 128;
#pragma unroll
        for (int i = 0; i < 2; i++) {
            int e = tid + i * 256;
            int kp = e >> 5, c4 = e & 31;
            cp16(&Bs0[buf * SM2_BS + kp * 132 + c4 * 4], &src[(size_t)kp * L_ + c4 * 4]);
        }
        CP_COMMIT();
    };

    issue(0, 0);

    float acc[2][4][4];
#pragma unroll 1
    for (int j = 0; j < 16; j++) {
        const int chunk = j >> 2, k0s = j & 3, buf = j & 1;
        if (k0s == 0) {
#pragma unroll
            for (int i = 0; i < 2; i++)
#pragma unroll
                for (int jj = 0; jj < 4; jj++)
#pragma unroll
                    for (int q = 0; q < 4; q++) acc[i][jj][q] = 0.0f;
        }
        if (j < 15) { issue(j + 1, buf ^ 1); CP_WAIT1(); } else { CP_WAIT0(); }
        __syncthreads();

        const unsigned* Bs = Bs0 + buf * SM2_BS;
#pragma unroll
        for (int kh = 0; kh < 2; kh++) {
            const int kbG = k0s * 16 + kh * 8;
            const int kbB = kh * 8;
            unsigned afr[2][4], bfr[4][2];
#pragma unroll
            for (int im = 0; im < 2; im++) {
                int r = warp_m * 32 + im * 16;
                afr[im][0] = hA[(r + lq) * 68 + kbG + lr];
                afr[im][1] = hA[(r + 8 + lq) * 68 + kbG + lr];
                afr[im][2] = hA[(r + lq) * 68 + kbG + 4 + lr];
                afr[im][3] = hA[(r + 8 + lq) * 68 + kbG + 4 + lr];
            }
#pragma unroll
            for (int jn = 0; jn < 4; jn++) {
                int c = warp_n * 32 + jn * 8 + lq;
                bfr[jn][0] = Bs[(kbB + lr) * 132 + c];
                bfr[jn][1] = Bs[(kbB + 4 + lr) * 132 + c];
            }
#pragma unroll
            for (int im = 0; im < 2; im++)
#pragma unroll
                for (int jn = 0; jn < 4; jn++) mma_bf16(acc[im][jn], afr[im], bfr[jn]);
        }

        if (k0s == 3) {
            const int n0c = chunk * 128;
#pragma unroll
            for (int im = 0; im < 2; im++) {
#pragma unroll
                for (int half = 0; half < 2; half++) {
                    int r = warp_m * 32 + im * 16 + half * 8 + lq;
#pragma unroll
                    for (int jn = 0; jn < 4; jn++) {
                        int c = warp_n * 32 + jn * 8 + lr * 2;
                        float x0 = 1.0f / (1.0f + __expf(-(acc[im][jn][half * 2 + 0] + bbt[n0c + c])));
                        float x1 = 1.0f / (1.0f + __expf(-(acc[im][jn][half * 2 + 1] + bbt[n0c + c + 1])));
                        // shifted layout: node n -> slot n+1 (scalar stores)
                        ph[r * PH_STRIDE + 1 + n0c + c] = __float2half(x0);
                        ph[r * PH_STRIDE + 2 + n0c + c] = __float2half(x1);
                    }
                }
            }
        }
        __syncthreads();
    }

    // mu phase: 64 rows x 32 subtrees (16 leaves) = 2048 tasks, 8/thread.
    // Warp = one row, lane = subtree s. Vectorized conflict-free tree reads:
    // depth 5 scalar @slot 32+s, depth 6 LDS.32 @64+2s, depth 7 LDS.64
    // @128+4s, depth 8 LDS.128 @256+8s.
    unsigned* muout = reinterpret_cast<unsigned*>(g_mu) + ((size_t)t * B_ + b0) * (L_ / 2);
#pragma unroll 1
    for (int i = 0; i < 8; i++) {
        int task = i * 256 + tid;
        int row = task >> 5;
        int s = task & 31;
        int l0 = s << 4;
        const __half* sp = ph + row * PH_STRIDE;

        float pref = 1.0f;
#pragma unroll
        for (int d = 0; d < 5; d++) {
            int slot = (1 << d) + (l0 >> (9 - d));
            float v = __half2float(sp[slot]);
            pref *= ((l0 >> (8 - d)) & 1) ? (1.0f - v) : v;
        }

        // depth 5 (1 node)
        float v5 = __half2float(sp[32 + s]);
        float c5[2];
        c5[0] = pref * v5;
        c5[1] = pref - c5[0];

        // depth 6 (2 nodes, one LDS.32)
        float2 f6 = __half22float2(*reinterpret_cast<const __half2*>(sp + 64 + 2 * s));
        float c6[4];
        c6[0] = c5[0] * f6.x; c6[1] = c5[0] - c6[0];
        c6[2] = c5[1] * f6.y; c6[3] = c5[1] - c6[2];

        // depth 7 (4 nodes, one LDS.64)
        uint2 r7 = *reinterpret_cast<const uint2*>(sp + 128 + 4 * s);
        float2 f7a = __half22float2(*reinterpret_cast<const __half2*>(&r7.x));
        float2 f7b = __half22float2(*reinterpret_cast<const __half2*>(&r7.y));
        float c7[8];
        c7[0] = c6[0] * f7a.x; c7[1] = c6[0] - c7[0];
        c7[2] = c6[1] * f7a.y; c7[3] = c6[1] - c7[2];
        c7[4] = c6[2] * f7b.x; c7[5] = c6[2] - c7[4];
        c7[6] = c6[3] * f7b.y; c7[7] = c6[3] - c7[6];

        // depth 8 (8 nodes, one LDS.128)
        uint4 r8 = *reinterpret_cast<const uint4*>(sp + 256 + 8 * s);
        float2 f8a = __half22float2(*reinterpret_cast<const __half2*>(&r8.x));
        float2 f8b = __half22float2(*reinterpret_cast<const __half2*>(&r8.y));
        float2 f8c = __half22float2(*reinterpret_cast<const __half2*>(&r8.z));
        float2 f8d = __half22float2(*reinterpret_cast<const __half2*>(&r8.w));
        float c8[16];
        c8[0]  = c7[0] * f8a.x; c8[1]  = c7[0] - c8[0];
        c8[2]  = c7[1] * f8a.y; c8[3]  = c7[1] - c8[2];
        c8[4]  = c7[2] * f8b.x; c8[5]  = c7[2] - c8[4];
        c8[6]  = c7[3] * f8b.y; c8[7]  = c7[3] - c8[6];
        c8[8]  = c7[4] * f8c.x; c8[9]  = c7[4] - c8[8];
        c8[10] = c7[5] * f8c.y; c8[11] = c7[5] - c8[10];
        c8[12] = c7[6] * f8d.x; c8[13] = c7[6] - c8[12];
        c8[14] = c7[7] * f8d.y; c8[15] = c7[7] - c8[14];

        unsigned w[8];
#pragma unroll
        for (int jj = 0; jj < 8; jj++) w[jj] = pkf(c8[2 * jj], c8[2 * jj + 1]);
        unsigned* dst = muout + (size_t)row * (L_ / 2) + s * 8;
        *reinterpret_cast<uint4*>(dst) = *reinterpret_cast<uint4*>(&w[0]);
        *reinterpret_cast<uint4*>(dst + 4) = *reinterpret_cast<uint4*>(&w[4]);
    }
}

// ---------------------------------------------------------------------------
// Leaf softmax -> packed layout g_lp[t][l/2][128] (bf16x2 over l, zero-pad).
// ---------------------------------------------------------------------------
__global__ __launch_bounds__(128) void leaf_softmax_pack(const float* __restrict__ pi) {
    const int row = blockIdx.x * 4 + (threadIdx.x >> 5);   // t*L + l
    const int lane = threadIdx.x & 31;
    const int t = row >> 9, l = row & (L_ - 1);
    const float* pr = pi + (size_t)row * C_;

    float v[4];
#pragma unroll
    for (int j = 0; j < 4; j++) {
        int c = lane + j * 32;
        v[j] = (c < C_) ? pr[c] : -1e30f;
    }
    float m = fmaxf(fmaxf(v[0], v[1]), fmaxf(v[2], v[3]));
#pragma unroll
    for (int o = 16; o; o >>= 1) m = fmaxf(m, __shfl_xor_sync(0xffffffffu, m, o));

    float e[4];
    float s = 0.0f;
#pragma unroll
    for (int j = 0; j < 4; j++) {
        int c = lane + j * 32;
        e[j] = (c < C_) ? __expf(v[j] - m) : 0.0f;
        s += e[j];
    }
#pragma unroll
    for (int o = 16; o; o >>= 1) s += __shfl_xor_sync(0xffffffffu, s, o);
    float inv = 1.0f / s;

    unsigned short* base = reinterpret_cast<unsigned short*>(g_lp);
    const size_t rowbase = ((size_t)t * (L_ / 2) + (l >> 1)) * 128;
#pragma unroll
    for (int j = 0; j < 4; j++) {
        int c = lane + j * 32;
        __nv_bfloat16 bv = __float2bfloat16((c < C_) ? e[j] * inv : 0.0f);
        base[(rowbase + c) * 2 + (l & 1)] = *reinterpret_cast<unsigned short*>(&bv);
    }
}

// ---------------------------------------------------------------------------
// Final contraction: part[t*2+ks] = mu[t][:, ks*256:+256] @ leafp chunk.
// 128x128 tile, K=256 per CTA, cp.async double-buffered. grid (8, T, 2).
// ---------------------------------------------------------------------------
__global__ __launch_bounds__(256) void final_bf16() {
    __shared__ unsigned As[2][128 * 20];
    __shared__ unsigned Bs[2][16 * 132];

    const int tid = threadIdx.x;
    const int wid = tid >> 5, lane = tid & 31;
    const int warp_m = wid >> 2, warp_n = wid & 3;
    const int lq = lane >> 2, lr = lane & 3;
    const int t = blockIdx.y;
    const int ks = blockIdx.z;
    const int b0 = blockIdx.x * 128;

    const unsigned* mu_u = reinterpret_cast<const unsigned*>(g_mu) + ((size_t)t * B_ + b0) * (L_ / 2);
    const unsigned* lpb = g_lp + (size_t)t * (L_ / 2) * 128;

    float acc[4][4][4];
#pragma unroll
    for (int i = 0; i < 4; i++)
#pragma unroll
        for (int j = 0; j < 4; j++)
#pragma unroll
            for (int q = 0; q < 4; q++) acc[i][j][q] = 0.0f;

    auto issue = [&](int kt, int buf) {
        const int kp0 = (ks * 256 + kt * 32) >> 1;
#pragma unroll
        for (int i = 0; i < 2; i++) {
            int e = tid + i * 256;
            int r = e >> 2, q = e & 3;
            cp16(&As[buf][r * 20 + q * 4], &mu_u[(size_t)r * (L_ / 2) + kp0 + q * 4]);
        }
#pragma unroll
        for (int i = 0; i < 2; i++) {
            int e = tid + i * 256;
            int kp = e >> 5, c4 = e & 31;
            cp16(&Bs[buf][kp * 132 + c4 * 4], &lpb[(size_t)(kp0 + kp) * 128 + c4 * 4]);
        }
        CP_COMMIT();
    };

    issue(0, 0);
#pragma unroll 1
    for (int kt = 0; kt < 8; kt++) {
        const int buf = kt & 1;
        if (kt < 7) { issue(kt + 1, buf ^ 1); CP_WAIT1(); } else { CP_WAIT0(); }
        __syncthreads();

#pragma unroll
        for (int kh = 0; kh < 2; kh++) {
            const int kb = kh * 8;
            unsigned bfr[4][2];
#pragma unroll
            for (int jn = 0; jn < 4; jn++) {
                int c = warp_n * 32 + jn * 8 + lq;
                bfr[jn][0] = Bs[buf][(kb + lr) * 132 + c];
                bfr[jn][1] = Bs[buf][(kb + 4 + lr) * 132 + c];
            }
#pragma unroll
            for (int im = 0; im < 4; im++) {
                int r = warp_m * 64 + im * 16;
                unsigned afr[4];
                afr[0] = As[buf][(r + lq) * 20 + kb + lr];
                afr[1] = As[buf][(r + 8 + lq) * 20 + kb + lr];
                afr[2] = As[buf][(r + lq) * 20 + kb + 4 + lr];
                afr[3] = As[buf][(r + 8 + lq) * 20 + kb + 4 + lr];
#pragma unroll
                for (int jn = 0; jn < 4; jn++) mma_bf16(acc[im][jn], afr, bfr[jn]);
            }
        }
        __syncthreads();
    }

    float* pb = g_part + (size_t)(t * FSPLIT + ks) * B_ * C_;
#pragma unroll
    for (int im = 0; im < 4; im++) {
#pragma unroll
        for (int half = 0; half < 2; half++) {
            int r = warp_m * 64 + im * 16 + half * 8 + lq;
#pragma unroll
            for (int jn = 0; jn < 4; jn++) {
                int c = warp_n * 32 + jn * 8 + lr * 2;
                if (c >= C_) continue;
                *reinterpret_cast<float2*>(&pb[(size_t)(b0 + r) * C_ + c]) =
                    make_float2(acc[im][jn][half * 2 + 0], acc[im][jn][half * 2 + 1]);
            }
        }
    }
}

// ---------------------------------------------------------------------------
// Deterministic reduction over KSPLIT partials + final log
// ---------------------------------------------------------------------------
__global__ __launch_bounds__(256) void reduce_log_kernel(float* __restrict__ out) {
    const int i = blockIdx.x * 256 + threadIdx.x;
    float s = 0.0f;
#pragma unroll
    for (int ks = 0; ks < KSPLIT; ks++) s += g_part[(size_t)ks * B_ * C_ + i];
    out[i] = logf(s * (1.0f / (float)(L_ * T_)));
}

extern "C" void kernel_launch(void* const* d_in, const int* in_sizes, int n_in,
                              void* d_out, int out_size) {
    const float* feat = (const float*)d_in[0];
    const float* W1 = (const float*)d_in[1];
    const float* b1 = (const float*)d_in[2];
    const float* W2 = (const float*)d_in[3];
    const float* b2 = (const float*)d_in[4];
    const float* pi = (const float*)d_in[5];
    float* out = (float*)d_out;

    cudaFuncSetAttribute(stage2_fused, cudaFuncAttributeMaxDynamicSharedMemorySize, SM2_BYTES);

    pack_inputs<<<dim3(2048, 3), 256>>>(feat, W1, W2);
    leaf_softmax_pack<<<(T_ * L_) / 4, 128>>>(pi);
    gemm1_bf16<<<dim3(B_ / 64, 1, T_), 256>>>(b1);
    stage2_fused<<<dim3(B_ / 64, T_), 256, SM2_BYTES>>>(b2);
    final_bf16<<<dim3(B_ / 128, T_, FSPLIT), 256>>>();
    reduce_log_kernel<<<(B_ * C_) / 256, 256>>>(out);
}

// round 10
// speedup vs baseline: 1.1199x; 1.0705x over previous
#include <cuda_runtime.h>
#include <cuda_bf16.h>
#include <cuda_fp16.h>
#include <math.h>

#define T_ 16
#define B_ 1024
#define F_DIM 512
#define H_ 128
#define L_ 512
#define C_ 100
#define KSPLIT 16

// Scratch (static device globals -- no allocation allowed)
__device__ unsigned g_lp[(size_t)T_ * (L_ / 2) * 128];    // 2 MB  packed leafp pairs
__device__ float g_part[(size_t)KSPLIT * B_ * C_];        // 6.5 MB
__device__ unsigned g_pf[(size_t)B_ * (F_DIM / 2)];       // 1 MB  packed feat pairs
__device__ unsigned g_pw1[(size_t)T_ * (F_DIM / 2) * H_]; // 2 MB  packed W1 pairs
__device__ unsigned g_pw2[(size_t)T_ * (H_ / 2) * L_];    // 2 MB  packed W2 pairs

__device__ __forceinline__ unsigned pkf(float lo, float hi) {
    __nv_bfloat162 h = __floats2bfloat162_rn(lo, hi);
    return *reinterpret_cast<unsigned*>(&h);
}

__device__ __forceinline__ void mma_bf16(float* d, const unsigned* a, const unsigned* b) {
    asm volatile(
        "mma.sync.aligned.m16n8k16.row.col.f32.bf16.bf16.f32 "
        "{%0,%1,%2,%3}, {%4,%5,%6,%7}, {%8,%9}, {%0,%1,%2,%3};\n"
        : "+f"(d[0]), "+f"(d[1]), "+f"(d[2]), "+f"(d[3])
        : "r"(a[0]), "r"(a[1]), "r"(a[2]), "r"(a[3]), "r"(b[0]), "r"(b[1]));
}

__device__ __forceinline__ void cp16(void* s, const void* g) {
    unsigned sa = (unsigned)__cvta_generic_to_shared(s);
    asm volatile("cp.async.ca.shared.global [%0], [%1], 16;\n" :: "r"(sa), "l"(g));
}
#define CP_COMMIT() asm volatile("cp.async.commit_group;\n")
#define CP_WAIT1()  asm volatile("cp.async.wait_group 1;\n")
#define CP_WAIT0()  asm volatile("cp.async.wait_group 0;\n")

// ---------------------------------------------------------------------------
// Pack feat / W1 / W2 into bf16x2 (pairs over k) MMA-ready layouts.
// ---------------------------------------------------------------------------
__global__ __launch_bounds__(256) void pack_inputs(const float* __restrict__ feat,
                                                   const float* __restrict__ W1,
                                                   const float* __restrict__ W2) {
    const int i = blockIdx.x * 256 + threadIdx.x;
    if (blockIdx.y == 0) {
        if (i < B_ * (F_DIM / 2)) {
            float2 v = *reinterpret_cast<const float2*>(&feat[(size_t)i * 2]);
            g_pf[i] = pkf(v.x, v.y);
        }
    } else if (blockIdx.y == 1) {
        int t = i >> 15, rem = i & 32767, f2 = rem >> 7, n = rem & 127;
        const float* base = W1 + ((size_t)t * F_DIM + 2 * f2) * H_ + n;
        g_pw1[i] = pkf(base[0], base[H_]);
    } else {
        int t = i >> 15, h2 = (i >> 9) & 63, l = i & 511;
        const float* base = W2 + ((size_t)t * H_ + 2 * h2) * L_ + l;
        g_pw2[i] = pkf(base[0], base[L_]);
    }
}

// ---------------------------------------------------------------------------
// Leaf softmax -> packed layout g_lp[t][l/2][128] (bf16x2 over l, zero-pad).
// ---------------------------------------------------------------------------
__global__ __launch_bounds__(128) void leaf_softmax_pack(const float* __restrict__ pi) {
    const int row = blockIdx.x * 4 + (threadIdx.x >> 5);   // t*L + l
    const int lane = threadIdx.x & 31;
    const int t = row >> 9, l = row & (L_ - 1);
    const float* pr = pi + (size_t)row * C_;

    float v[4];
#pragma unroll
    for (int j = 0; j < 4; j++) {
        int c = lane + j * 32;
        v[j] = (c < C_) ? pr[c] : -1e30f;
    }
    float m = fmaxf(fmaxf(v[0], v[1]), fmaxf(v[2], v[3]));
#pragma unroll
    for (int o = 16; o; o >>= 1) m = fmaxf(m, __shfl_xor_sync(0xffffffffu, m, o));

    float e[4];
    float s = 0.0f;
#pragma unroll
    for (int j = 0; j < 4; j++) {
        int c = lane + j * 32;
        e[j] = (c < C_) ? __expf(v[j] - m) : 0.0f;
        s += e[j];
    }
#pragma unroll
    for (int o = 16; o; o >>= 1) s += __shfl_xor_sync(0xffffffffu, s, o);
    float inv = 1.0f / s;

    unsigned short* base = reinterpret_cast<unsigned short*>(g_lp);
    const size_t rowbase = ((size_t)t * (L_ / 2) + (l >> 1)) * 128;
#pragma unroll
    for (int j = 0; j < 4; j++) {
        int c = lane + j * 32;
        __nv_bfloat16 bv = __float2bfloat16((c < C_) ? e[j] * inv : 0.0f);
        base[(rowbase + c) * 2 + (l & 1)] = *reinterpret_cast<unsigned short*>(&bv);
    }
}

// ---------------------------------------------------------------------------
// Fully fused per-(tree, 64-row) kernel:
//   phase1: h  = relu(feat @ W1 + b1)      -> hA (smem, bf16 pairs)
//   phase2: p  = sigmoid(h @ W2 + b2)      -> ph (smem fp16, shifted nodes)
//   phase3: mu = routing products          -> in-place over ph (bf16 pairs)
//   phase4: part[t] = mu @ leafp[t]        -> g_part
// grid (B/64, T) = 256 CTAs, 256 threads, 100.8KB smem (2 CTAs/SM).
// smem: hA [64*68] | Bs0 [2][16*132] | union( As [2][64*20] , ph [64*520 fp16] )
// ---------------------------------------------------------------------------
#define MS_HA (64 * 68)
#define MS_BS (16 * 132)
#define MS_AS (64 * 20)
#define PH_U32 (64 * 260)
#define PH_STRIDE 520
#define SMEM_BYTES ((MS_HA + 2 * MS_BS + PH_U32) * 4)

__global__ __launch_bounds__(256, 2) void forest_fused(const float* __restrict__ b1,
                                                       const float* __restrict__ b2) {
    extern __shared__ unsigned sm[];
    unsigned* hA = sm;                          // [64][68]
    unsigned* Bs0 = sm + MS_HA;                 // [2][16*132]
    unsigned* uni = sm + MS_HA + 2 * MS_BS;     // union: As[2][64*20] / ph
    __half* ph = reinterpret_cast<__half*>(uni);

    const int tid = threadIdx.x;
    const int wid = tid >> 5, lane = tid & 31;
    const int warp_m = wid >> 2, warp_n = wid & 3;   // 2x4 warps, 32x32 tiles
    const int lq = lane >> 2, lr = lane & 3;
    const int t = blockIdx.y;
    const int b0 = blockIdx.x * 64;

    float acc[2][4][4];

    // ================= phase 1: GEMM1 -> hA =================
    {
        const unsigned* pf = g_pf + (size_t)b0 * (F_DIM / 2);
        const unsigned* pw = g_pw1 + (size_t)t * (F_DIM / 2) * H_;
        const float* bb = b1 + (size_t)t * H_;

#pragma unroll
        for (int i = 0; i < 2; i++)
#pragma unroll
            for (int j = 0; j < 4; j++)
#pragma unroll
                for (int q = 0; q < 4; q++) acc[i][j][q] = 0.0f;

        auto issue1 = [&](int kt, int buf) {
            const int kp0 = kt * 16;
            {
                int r = tid >> 2, q = tid & 3;
                cp16(&uni[buf * MS_AS + r * 20 + q * 4],
                     &pf[(size_t)r * (F_DIM / 2) + kp0 + q * 4]);
            }
#pragma unroll
            for (int i = 0; i < 2; i++) {
                int e = tid + i * 256;
                int kp = e >> 5, c4 = e & 31;
                cp16(&Bs0[buf * MS_BS + kp * 132 + c4 * 4],
                     &pw[(size_t)(kp0 + kp) * H_ + c4 * 4]);
            }
            CP_COMMIT();
        };

        issue1(0, 0);
#pragma unroll 1
        for (int kt = 0; kt < 16; kt++) {
            const int buf = kt & 1;
            if (kt < 15) { issue1(kt + 1, buf ^ 1); CP_WAIT1(); } else { CP_WAIT0(); }
            __syncthreads();

            const unsigned* As = uni + buf * MS_AS;
            const unsigned* Bs = Bs0 + buf * MS_BS;
#pragma unroll
            for (int kh = 0; kh < 2; kh++) {
                const int kb = kh * 8;
                unsigned afr[2][4], bfr[4][2];
#pragma unroll
                for (int im = 0; im < 2; im++) {
                    int r = warp_m * 32 + im * 16;
                    afr[im][0] = As[(r + lq) * 20 + kb + lr];
                    afr[im][1] = As[(r + 8 + lq) * 20 + kb + lr];
                    afr[im][2] = As[(r + lq) * 20 + kb + 4 + lr];
                    afr[im][3] = As[(r + 8 + lq) * 20 + kb + 4 + lr];
                }
#pragma unroll
                for (int jn = 0; jn < 4; jn++) {
                    int c = warp_n * 32 + jn * 8 + lq;
                    bfr[jn][0] = Bs[(kb + lr) * 132 + c];
                    bfr[jn][1] = Bs[(kb + 4 + lr) * 132 + c];
                }
#pragma unroll
                for (int im = 0; im < 2; im++)
#pragma unroll
                    for (int jn = 0; jn < 4; jn++) mma_bf16(acc[im][jn], afr[im], bfr[jn]);
            }
            __syncthreads();
        }

        // epilogue -> hA (bf16 pairs over h)
#pragma unroll
        for (int im = 0; im < 2; im++) {
#pragma unroll
            for (int half = 0; half < 2; half++) {
                int r = warp_m * 32 + im * 16 + half * 8 + lq;
#pragma unroll
                for (int jn = 0; jn < 4; jn++) {
                    int c = warp_n * 32 + jn * 8 + lr * 2;
                    float x0 = fmaxf(acc[im][jn][half * 2 + 0] + bb[c], 0.0f);
                    float x1 = fmaxf(acc[im][jn][half * 2 + 1] + bb[c + 1], 0.0f);
                    hA[r * 68 + (c >> 1)] = pkf(x0, x1);
                }
            }
        }
        __syncthreads();
    }

    // ================= phase 2: GEMM2 + sigmoid -> ph =================
    {
        const unsigned* pw = g_pw2 + (size_t)t * (H_ / 2) * L_;
        const float* bbt = b2 + (size_t)t * L_;

        auto issue2 = [&](int j, int buf) {
            const int chunk = j >> 2, k0s = j & 3;
            const unsigned* src = pw + (size_t)(k0s * 16) * L_ + chunk * 128;
#pragma unroll
            for (int i = 0; i < 2; i++) {
                int e = tid + i * 256;
                int kp = e >> 5, c4 = e & 31;
                cp16(&Bs0[buf * MS_BS + kp * 132 + c4 * 4], &src[(size_t)kp * L_ + c4 * 4]);
            }
            CP_COMMIT();
        };

        issue2(0, 0);
#pragma unroll 1
        for (int j = 0; j < 16; j++) {
            const int chunk = j >> 2, k0s = j & 3, buf = j & 1;
            if (k0s == 0) {
#pragma unroll
                for (int i = 0; i < 2; i++)
#pragma unroll
                    for (int jj = 0; jj < 4; jj++)
#pragma unroll
                        for (int q = 0; q < 4; q++) acc[i][jj][q] = 0.0f;
            }
            if (j < 15) { issue2(j + 1, buf ^ 1); CP_WAIT1(); } else { CP_WAIT0(); }
            __syncthreads();

            const unsigned* Bs = Bs0 + buf * MS_BS;
#pragma unroll
            for (int kh = 0; kh < 2; kh++) {
                const int kbG = k0s * 16 + kh * 8;
                const int kbB = kh * 8;
                unsigned afr[2][4], bfr[4][2];
#pragma unroll
                for (int im = 0; im < 2; im++) {
                    int r = warp_m * 32 + im * 16;
                    afr[im][0] = hA[(r + lq) * 68 + kbG + lr];
                    afr[im][1] = hA[(r + 8 + lq) * 68 + kbG + lr];
                    afr[im][2] = hA[(r + lq) * 68 + kbG + 4 + lr];
                    afr[im][3] = hA[(r + 8 + lq) * 68 + kbG + 4 + lr];
                }
#pragma unroll
                for (int jn = 0; jn < 4; jn++) {
                    int c = warp_n * 32 + jn * 8 + lq;
                    bfr[jn][0] = Bs[(kbB + lr) * 132 + c];
                    bfr[jn][1] = Bs[(kbB + 4 + lr) * 132 + c];
                }
#pragma unroll
                for (int im = 0; im < 2; im++)
#pragma unroll
                    for (int jn = 0; jn < 4; jn++) mma_bf16(acc[im][jn], afr[im], bfr[jn]);
            }

            if (k0s == 3) {
                const int n0c = chunk * 128;
#pragma unroll
                for (int im = 0; im < 2; im++) {
#pragma unroll
                    for (int half = 0; half < 2; half++) {
                        int r = warp_m * 32 + im * 16 + half * 8 + lq;
#pragma unroll
                        for (int jn = 0; jn < 4; jn++) {
                            int c = warp_n * 32 + jn * 8 + lr * 2;
                            float x0 = 1.0f / (1.0f + __expf(-(acc[im][jn][half * 2 + 0] + bbt[n0c + c])));
                            float x1 = 1.0f / (1.0f + __expf(-(acc[im][jn][half * 2 + 1] + bbt[n0c + c + 1])));
                            // shifted node layout: node n -> slot n+1
                            ph[r * PH_STRIDE + 1 + n0c + c] = __float2half(x0);
                            ph[r * PH_STRIDE + 2 + n0c + c] = __float2half(x1);
                        }
                    }
                }
            }
            __syncthreads();
        }
    }

    // ================= phase 3: mu in-place over ph =================
    // Warp = one row, lane = subtree s (16 leaves). All loads precede all
    // stores within the warp, so overwriting the row's node slots is safe.
#pragma unroll 1
    for (int i = 0; i < 8; i++) {
        int task = i * 256 + tid;
        int row = task >> 5;
        int s = task & 31;
        int l0 = s << 4;
        const __half* sp = ph + row * PH_STRIDE;

        float pref = 1.0f;
#pragma unroll
        for (int d = 0; d < 5; d++) {
            int slot = (1 << d) + (l0 >> (9 - d));
            float v = __half2float(sp[slot]);
            pref *= ((l0 >> (8 - d)) & 1) ? (1.0f - v) : v;
        }

        float v5 = __half2float(sp[32 + s]);
        float c5[2];
        c5[0] = pref * v5;
        c5[1] = pref - c5[0];

        float2 f6 = __half22float2(*reinterpret_cast<const __half2*>(sp + 64 + 2 * s));
        float c6[4];
        c6[0] = c5[0] * f6.x; c6[1] = c5[0] - c6[0];
        c6[2] = c5[1] * f6.y; c6[3] = c5[1] - c6[2];

        uint2 r7 = *reinterpret_cast<const uint2*>(sp + 128 + 4 * s);
        float2 f7a = __half22float2(*reinterpret_cast<const __half2*>(&r7.x));
        float2 f7b = __half22float2(*reinterpret_cast<const __half2*>(&r7.y));
        float c7[8];
        c7[0] = c6[0] * f7a.x; c7[1] = c6[0] - c7[0];
        c7[2] = c6[1] * f7a.y; c7[3] = c6[1] - c7[2];
        c7[4] = c6[2] * f7b.x; c7[5] = c6[2] - c7[4];
        c7[6] = c6[3] * f7b.y; c7[7] = c6[3] - c7[6];

        uint4 r8 = *reinterpret_cast<const uint4*>(sp + 256 + 8 * s);
        float2 f8a = __half22float2(*reinterpret_cast<const __half2*>(&r8.x));
        float2 f8b = __half22float2(*reinterpret_cast<const __half2*>(&r8.y));
        float2 f8c = __half22float2(*reinterpret_cast<const __half2*>(&r8.z));
        float2 f8d = __half22float2(*reinterpret_cast<const __half2*>(&r8.w));
        float c8[16];
        c8[0]  = c7[0] * f8a.x; c8[1]  = c7[0] - c8[0];
        c8[2]  = c7[1] * f8a.y; c8[3]  = c7[1] - c8[2];
        c8[4]  = c7[2] * f8b.x; c8[5]  = c7[2] - c8[4];
        c8[6]  = c7[3] * f8b.y; c8[7]  = c7[3] - c8[6];
        c8[8]  = c7[4] * f8c.x; c8[9]  = c7[4] - c8[8];
        c8[10] = c7[5] * f8c.y; c8[11] = c7[5] - c8[10];
        c8[12] = c7[6] * f8d.x; c8[13] = c7[6] - c8[12];
        c8[14] = c7[7] * f8d.y; c8[15] = c7[7] - c8[14];

        // write mu as bf16 pairs over l, in-place into this row (u32 slots s*8..s*8+7)
        unsigned w[8];
#pragma unroll
        for (int jj = 0; jj < 8; jj++) w[jj] = pkf(c8[2 * jj], c8[2 * jj + 1]);
        unsigned* rowbuf = uni + row * 260;
        *reinterpret_cast<uint4*>(rowbuf + s * 8) = *reinterpret_cast<uint4*>(&w[0]);
        *reinterpret_cast<uint4*>(rowbuf + s * 8 + 4) = *reinterpret_cast<uint4*>(&w[4]);
    }
    __syncthreads();

    // ================= phase 4: GEMM3 (mu @ leafp) -> g_part =================
    {
        const unsigned* lpb = g_lp + (size_t)t * (L_ / 2) * 128;

#pragma unroll
        for (int i = 0; i < 2; i++)
#pragma unroll
            for (int j = 0; j < 4; j++)
#pragma unroll
                for (int q = 0; q < 4; q++) acc[i][j][q] = 0.0f;

        auto issue3 = [&](int kt, int buf) {
#pragma unroll
            for (int i = 0; i < 2; i++) {
                int e = tid + i * 256;
                int kp = e >> 5, c4 = e & 31;
                cp16(&Bs0[buf * MS_BS + kp * 132 + c4 * 4],
                     &lpb[(size_t)(kt * 16 + kp) * 128 + c4 * 4]);
            }
            CP_COMMIT();
        };

        issue3(0, 0);
#pragma unroll 1
        for (int kt = 0; kt < 16; kt++) {
            const int buf = kt & 1;
            if (kt < 15) { issue3(kt + 1, buf ^ 1); CP_WAIT1(); } else { CP_WAIT0(); }
            __syncthreads();

            const unsigned* Bs = Bs0 + buf * MS_BS;
#pragma unroll
            for (int kh = 0; kh < 2; kh++) {
                const int kbA = kt * 16 + kh * 8;   // A pair base (global, in smem)
                const int kbB = kh * 8;
                unsigned afr[2][4], bfr[4][2];
#pragma unroll
                for (int im = 0; im < 2; im++) {
                    int r = warp_m * 32 + im * 16;
                    afr[im][0] = uni[(r + lq) * 260 + kbA + lr];
                    afr[im][1] = uni[(r + 8 + lq) * 260 + kbA + lr];
                    afr[im][2] = uni[(r + lq) * 260 + kbA + 4 + lr];
                    afr[im][3] = uni[(r + 8 + lq) * 260 + kbA + 4 + lr];
                }
#pragma unroll
                for (int jn = 0; jn < 4; jn++) {
                    int c = warp_n * 32 + jn * 8 + lq;
                    bfr[jn][0] = Bs[(kbB + lr) * 132 + c];
                    bfr[jn][1] = Bs[(kbB + 4 + lr) * 132 + c];
                }
#pragma unroll
                for (int im = 0; im < 2; im++)
#pragma unroll
                    for (int jn = 0; jn < 4; jn++) mma_bf16(acc[im][jn], afr[im], bfr[jn]);
            }
            __syncthreads();
        }

        float* pb = g_part + (size_t)t * B_ * C_;
#pragma unroll
        for (int im = 0; im < 2; im++) {
#pragma unroll
            for (int half = 0; half < 2; half++) {
                int r = warp_m * 32 + im * 16 + half * 8 + lq;
#pragma unroll
                for (int jn = 0; jn < 4; jn++) {
                    int c = warp_n * 32 + jn * 8 + lr * 2;
                    if (c >= C_) continue;
                    *reinterpret_cast<float2*>(&pb[(size_t)(b0 + r) * C_ + c]) =
                        make_float2(acc[im][jn][half * 2 + 0], acc[im][jn][half * 2 + 1]);
                }
            }
        }
    }
}

// ---------------------------------------------------------------------------
// Deterministic reduction over trees + final log
// ---------------------------------------------------------------------------
__global__ __launch_bounds__(256) void reduce_log_kernel(float* __restrict__ out) {
    const int i = blockIdx.x * 256 + threadIdx.x;
    float s = 0.0f;
#pragma unroll
    for (int ks = 0; ks < KSPLIT; ks++) s += g_part[(size_t)ks * B_ * C_ + i];
    out[i] = logf(s * (1.0f / (float)(L_ * T_)));
}

extern "C" void kernel_launch(void* const* d_in, const int* in_sizes, int n_in,
                              void* d_out, int out_size) {
    const float* feat = (const float*)d_in[0];
    const float* W1 = (const float*)d_in[1];
    const float* b1 = (const float*)d_in[2];
    const float* W2 = (const float*)d_in[3];
    const float* b2 = (const float*)d_in[4];
    const float* pi = (const float*)d_in[5];
    float* out = (float*)d_out;

    cudaFuncSetAttribute(forest_fused, cudaFuncAttributeMaxDynamicSharedMemorySize, SMEM_BYTES);

    pack_inputs<<<dim3(2048, 3), 256>>>(feat, W1, W2);
    leaf_softmax_pack<<<(T_ * L_) / 4, 128>>>(pi);
    forest_fused<<<dim3(B_ / 64, T_), 256, SMEM_BYTES>>>(b1, b2);
    reduce_log_kernel<<<(B_ * C_) / 256, 256>>>(out);
}

// round 11
// speedup vs baseline: 1.1286x; 1.0078x over previous
#include <cuda_runtime.h>
#include <cuda_bf16.h>
#include <cuda_fp16.h>
#include <math.h>

#define T_ 16
#define B_ 1024
#define F_DIM 512
#define H_ 128
#define L_ 512
#define C_ 100
#define KSPLIT 16

// Scratch (static device globals -- no allocation allowed)
__device__ unsigned g_lp[(size_t)T_ * (L_ / 2) * 128];    // 2 MB  packed leafp pairs
__device__ float g_part[(size_t)KSPLIT * B_ * C_];        // 6.5 MB
__device__ unsigned g_pf[(size_t)B_ * (F_DIM / 2)];       // 1 MB  packed feat pairs
__device__ unsigned g_pw1[(size_t)T_ * (F_DIM / 2) * H_]; // 2 MB  packed W1 pairs
__device__ unsigned g_pw2[(size_t)T_ * (H_ / 2) * L_];    // 2 MB  packed W2 pairs

__device__ __forceinline__ unsigned pkf(float lo, float hi) {
    __nv_bfloat162 h = __floats2bfloat162_rn(lo, hi);
    return *reinterpret_cast<unsigned*>(&h);
}

__device__ __forceinline__ void mma_bf16(float* d, const unsigned* a, const unsigned* b) {
    asm volatile(
        "mma.sync.aligned.m16n8k16.row.col.f32.bf16.bf16.f32 "
        "{%0,%1,%2,%3}, {%4,%5,%6,%7}, {%8,%9}, {%0,%1,%2,%3};\n"
        : "+f"(d[0]), "+f"(d[1]), "+f"(d[2]), "+f"(d[3])
        : "r"(a[0]), "r"(a[1]), "r"(a[2]), "r"(a[3]), "r"(b[0]), "r"(b[1]));
}

__device__ __forceinline__ void cp16(void* s, const void* g) {
    unsigned sa = (unsigned)__cvta_generic_to_shared(s);
    asm volatile("cp.async.ca.shared.global [%0], [%1], 16;\n" :: "r"(sa), "l"(g));
}
#define CP_COMMIT() asm volatile("cp.async.commit_group;\n")
#define CP_WAIT1()  asm volatile("cp.async.wait_group 1;\n")
#define CP_WAIT0()  asm volatile("cp.async.wait_group 0;\n")

// ---------------------------------------------------------------------------
// Merged prep: blocks [0, 6144) pack feat/W1/W2; blocks [6144, 7168) do the
// leaf softmax into the packed g_lp layout. One launch.
// ---------------------------------------------------------------------------
__global__ __launch_bounds__(256) void prep_kernel(const float* __restrict__ feat,
                                                   const float* __restrict__ W1,
                                                   const float* __restrict__ W2,
                                                   const float* __restrict__ pi) {
    const int bx = blockIdx.x;
    const int tid = threadIdx.x;
    if (bx < 6144) {
        const int sel = bx >> 11;           // 0: feat, 1: W1, 2: W2
        const int i = (bx & 2047) * 256 + tid;
        if (sel == 0) {
            if (i < B_ * (F_DIM / 2)) {
                float2 v = *reinterpret_cast<const float2*>(&feat[(size_t)i * 2]);
                g_pf[i] = pkf(v.x, v.y);
            }
        } else if (sel == 1) {
            int t = i >> 15, rem = i & 32767, f2 = rem >> 7, n = rem & 127;
            const float* base = W1 + ((size_t)t * F_DIM + 2 * f2) * H_ + n;
            g_pw1[i] = pkf(base[0], base[H_]);
        } else {
            int t = i >> 15, h2 = (i >> 9) & 63, l = i & 511;
            const float* base = W2 + ((size_t)t * H_ + 2 * h2) * L_ + l;
            g_pw2[i] = pkf(base[0], base[L_]);
        }
    } else {
        // softmax: 8 warps/block, one (t,l) row each
        const int row = (bx - 6144) * 8 + (tid >> 5);   // t*L + l
        const int lane = tid & 31;
        const int t = row >> 9, l = row & (L_ - 1);
        const float* pr = pi + (size_t)row * C_;

        float v[4];
#pragma unroll
        for (int j = 0; j < 4; j++) {
            int c = lane + j * 32;
            v[j] = (c < C_) ? pr[c] : -1e30f;
        }
        float m = fmaxf(fmaxf(v[0], v[1]), fmaxf(v[2], v[3]));
#pragma unroll
        for (int o = 16; o; o >>= 1) m = fmaxf(m, __shfl_xor_sync(0xffffffffu, m, o));

        float e[4];
        float s = 0.0f;
#pragma unroll
        for (int j = 0; j < 4; j++) {
            int c = lane + j * 32;
            e[j] = (c < C_) ? __expf(v[j] - m) : 0.0f;
            s += e[j];
        }
#pragma unroll
        for (int o = 16; o; o >>= 1) s += __shfl_xor_sync(0xffffffffu, s, o);
        float inv = 1.0f / s;

        unsigned short* base = reinterpret_cast<unsigned short*>(g_lp);
        const size_t rowbase = ((size_t)t * (L_ / 2) + (l >> 1)) * 128;
#pragma unroll
        for (int j = 0; j < 4; j++) {
            int c = lane + j * 32;
            __nv_bfloat16 bv = __float2bfloat16((c < C_) ? e[j] * inv : 0.0f);
            base[(rowbase + c) * 2 + (l & 1)] = *reinterpret_cast<unsigned short*>(&bv);
        }
    }
}

// ---------------------------------------------------------------------------
// Fully fused per-(tree, 64-row) kernel, 3-stage cp.async, ONE sync per tile:
//   phase1: h  = relu(feat @ W1 + b1)      -> hA (smem, bf16 pairs)
//   phase2: p  = sigmoid(h @ W2 + b2)      -> ph (smem fp16, shifted nodes)
//   phase3: mu = routing products          -> in-place over ph (bf16 pairs)
//   phase4: part[t] = mu @ leafp[t]        -> g_part
// grid (B/64, T) = 256 CTAs, 256 threads, 106.8KB smem (2 CTAs/SM).
// smem: hA [64*68] | Bs0 [3][16*132] | union( As [3][64*20] , ph [64*520 fp16] )
// ---------------------------------------------------------------------------
#define MS_HA (64 * 68)
#define MS_BS (16 * 132)
#define MS_AS (64 * 20)
#define PH_U32 (64 * 260)
#define PH_STRIDE 520
#define SMEM_BYTES ((MS_HA + 3 * MS_BS + PH_U32) * 4)

__global__ __launch_bounds__(256, 2) void forest_fused(const float* __restrict__ b1,
                                                       const float* __restrict__ b2) {
    extern __shared__ unsigned sm[];
    unsigned* hA = sm;                          // [64][68]
    unsigned* Bs0 = sm + MS_HA;                 // [3][16*132]
    unsigned* uni = sm + MS_HA + 3 * MS_BS;     // union: As[3][64*20] / ph
    __half* ph = reinterpret_cast<__half*>(uni);

    const int tid = threadIdx.x;
    const int wid = tid >> 5, lane = tid & 31;
    const int warp_m = wid >> 2, warp_n = wid & 3;   // 2x4 warps, 32x32 tiles
    const int lq = lane >> 2, lr = lane & 3;
    const int t = blockIdx.y;
    const int b0 = blockIdx.x * 64;

    float acc[2][4][4];

    // ================= phase 1: GEMM1 -> hA =================
    {
        const unsigned* pf = g_pf + (size_t)b0 * (F_DIM / 2);
        const unsigned* pw = g_pw1 + (size_t)t * (F_DIM / 2) * H_;
        const float* bb = b1 + (size_t)t * H_;

#pragma unroll
        for (int i = 0; i < 2; i++)
#pragma unroll
            for (int j = 0; j < 4; j++)
#pragma unroll
                for (int q = 0; q < 4; q++) acc[i][j][q] = 0.0f;

        auto issue1 = [&](int kt, int buf) {
            const int kp0 = kt * 16;
            {
                int r = tid >> 2, q = tid & 3;
                cp16(&uni[buf * MS_AS + r * 20 + q * 4],
                     &pf[(size_t)r * (F_DIM / 2) + kp0 + q * 4]);
            }
#pragma unroll
            for (int i = 0; i < 2; i++) {
                int e = tid + i * 256;
                int kp = e >> 5, c4 = e & 31;
                cp16(&Bs0[buf * MS_BS + kp * 132 + c4 * 4],
                     &pw[(size_t)(kp0 + kp) * H_ + c4 * 4]);
            }
            CP_COMMIT();
        };

        issue1(0, 0);
        issue1(1, 1);
#pragma unroll 1
        for (int kt = 0; kt < 16; kt++) {
            const int buf = kt % 3;
            if (kt == 15) { CP_WAIT0(); } else { CP_WAIT1(); }
            __syncthreads();

            const unsigned* As = uni + buf * MS_AS;
            const unsigned* Bs = Bs0 + buf * MS_BS;
#pragma unroll
            for (int kh = 0; kh < 2; kh++) {
                const int kb = kh * 8;
                unsigned afr[2][4], bfr[4][2];
#pragma unroll
                for (int im = 0; im < 2; im++) {
                    int r = warp_m * 32 + im * 16;
                    afr[im][0] = As[(r + lq) * 20 + kb + lr];
                    afr[im][1] = As[(r + 8 + lq) * 20 + kb + lr];
                    afr[im][2] = As[(r + lq) * 20 + kb + 4 + lr];
                    afr[im][3] = As[(r + 8 + lq) * 20 + kb + 4 + lr];
                }
#pragma unroll
                for (int jn = 0; jn < 4; jn++) {
                    int c = warp_n * 32 + jn * 8 + lq;
                    bfr[jn][0] = Bs[(kb + lr) * 132 + c];
                    bfr[jn][1] = Bs[(kb + 4 + lr) * 132 + c];
                }
#pragma unroll
                for (int im = 0; im < 2; im++)
#pragma unroll
                    for (int jn = 0; jn < 4; jn++) mma_bf16(acc[im][jn], afr[im], bfr[jn]);
            }
            if (kt + 2 < 16) issue1(kt + 2, (kt + 2) % 3);
        }
        __syncthreads();   // all compute done before hA epilogue overwrite check

        // epilogue -> hA (bf16 pairs over h)
#pragma unroll
        for (int im = 0; im < 2; im++) {
#pragma unroll
            for (int half = 0; half < 2; half++) {
                int r = warp_m * 32 + im * 16 + half * 8 + lq;
#pragma unroll
                for (int jn = 0; jn < 4; jn++) {
                    int c = warp_n * 32 + jn * 8 + lr * 2;
                    float x0 = fmaxf(acc[im][jn][half * 2 + 0] + bb[c], 0.0f);
                    float x1 = fmaxf(acc[im][jn][half * 2 + 1] + bb[c + 1], 0.0f);
                    hA[r * 68 + (c >> 1)] = pkf(x0, x1);
                }
            }
        }
        __syncthreads();
    }

    // ================= phase 2: GEMM2 + sigmoid -> ph =================
    {
        const unsigned* pw = g_pw2 + (size_t)t * (H_ / 2) * L_;
        const float* bbt = b2 + (size_t)t * L_;

        auto issue2 = [&](int j, int buf) {
            const int chunk = j >> 2, k0s = j & 3;
            const unsigned* src = pw + (size_t)(k0s * 16) * L_ + chunk * 128;
#pragma unroll
            for (int i = 0; i < 2; i++) {
                int e = tid + i * 256;
                int kp = e >> 5, c4 = e & 31;
                cp16(&Bs0[buf * MS_BS + kp * 132 + c4 * 4], &src[(size_t)kp * L_ + c4 * 4]);
            }
            CP_COMMIT();
        };

        issue2(0, 0);
        issue2(1, 1);
#pragma unroll 1
        for (int j = 0; j < 16; j++) {
            const int chunk = j >> 2, k0s = j & 3, buf = j % 3;
            if (k0s == 0) {
#pragma unroll
                for (int i = 0; i < 2; i++)
#pragma unroll
                    for (int jj = 0; jj < 4; jj++)
#pragma unroll
                        for (int q = 0; q < 4; q++) acc[i][jj][q] = 0.0f;
            }
            if (j == 15) { CP_WAIT0(); } else { CP_WAIT1(); }
            __syncthreads();

            const unsigned* Bs = Bs0 + buf * MS_BS;
#pragma unroll
            for (int kh = 0; kh < 2; kh++) {
                const int kbG = k0s * 16 + kh * 8;
                const int kbB = kh * 8;
                unsigned afr[2][4], bfr[4][2];
#pragma unroll
                for (int im = 0; im < 2; im++) {
                    int r = warp_m * 32 + im * 16;
                    afr[im][0] = hA[(r + lq) * 68 + kbG + lr];
                    afr[im][1] = hA[(r + 8 + lq) * 68 + kbG + lr];
                    afr[im][2] = hA[(r + lq) * 68 + kbG + 4 + lr];
                    afr[im][3] = hA[(r + 8 + lq) * 68 + kbG + 4 + lr];
                }
#pragma unroll
                for (int jn = 0; jn < 4; jn++) {
                    int c = warp_n * 32 + jn * 8 + lq;
                    bfr[jn][0] = Bs[(kbB + lr) * 132 + c];
                    bfr[jn][1] = Bs[(kbB + 4 + lr) * 132 + c];
                }
#pragma unroll
                for (int im = 0; im < 2; im++)
#pragma unroll
                    for (int jn = 0; jn < 4; jn++) mma_bf16(acc[im][jn], afr[im], bfr[jn]);
            }

            if (k0s == 3) {
                const int n0c = chunk * 128;
#pragma unroll
                for (int im = 0; im < 2; im++) {
#pragma unroll
                    for (int half = 0; half < 2; half++) {
                        int r = warp_m * 32 + im * 16 + half * 8 + lq;
#pragma unroll
                        for (int jn = 0; jn < 4; jn++) {
                            int c = warp_n * 32 + jn * 8 + lr * 2;
                            float x0 = 1.0f / (1.0f + __expf(-(acc[im][jn][half * 2 + 0] + bbt[n0c + c])));
                            float x1 = 1.0f / (1.0f + __expf(-(acc[im][jn][half * 2 + 1] + bbt[n0c + c + 1])));
                            // shifted node layout: node n -> slot n+1
                            ph[r * PH_STRIDE + 1 + n0c + c] = __float2half(x0);
                            ph[r * PH_STRIDE + 2 + n0c + c] = __float2half(x1);
                        }
                    }
                }
            }
            if (j + 2 < 16) issue2(j + 2, (j + 2) % 3);
        }
        __syncthreads();
    }

    // ================= phase 3: mu in-place over ph =================
    // Warp = one row, lane = subtree s (16 leaves). All loads precede all
    // stores within the warp, so overwriting the row's node slots is safe.
#pragma unroll 1
    for (int i = 0; i < 8; i++) {
        int task = i * 256 + tid;
        int row = task >> 5;
        int s = task & 31;
        int l0 = s << 4;
        const __half* sp = ph + row * PH_STRIDE;

        float pref = 1.0f;
#pragma unroll
        for (int d = 0; d < 5; d++) {
            int slot = (1 << d) + (l0 >> (9 - d));
            float v = __half2float(sp[slot]);
            pref *= ((l0 >> (8 - d)) & 1) ? (1.0f - v) : v;
        }

        float v5 = __half2float(sp[32 + s]);
        float c5[2];
        c5[0] = pref * v5;
        c5[1] = pref - c5[0];

        float2 f6 = __half22float2(*reinterpret_cast<const __half2*>(sp + 64 + 2 * s));
        float c6[4];
        c6[0] = c5[0] * f6.x; c6[1] = c5[0] - c6[0];
        c6[2] = c5[1] * f6.y; c6[3] = c5[1] - c6[2];

        uint2 r7 = *reinterpret_cast<const uint2*>(sp + 128 + 4 * s);
        float2 f7a = __half22float2(*reinterpret_cast<const __half2*>(&r7.x));
        float2 f7b = __half22float2(*reinterpret_cast<const __half2*>(&r7.y));
        float c7[8];
        c7[0] = c6[0] * f7a.x; c7[1] = c6[0] - c7[0];
        c7[2] = c6[1] * f7a.y; c7[3] = c6[1] - c7[2];
        c7[4] = c6[2] * f7b.x; c7[5] = c6[2] - c7[4];
        c7[6] = c6[3] * f7b.y; c7[7] = c6[3] - c7[6];

        uint4 r8 = *reinterpret_cast<const uint4*>(sp + 256 + 8 * s);
        float2 f8a = __half22float2(*reinterpret_cast<const __half2*>(&r8.x));
        float2 f8b = __half22float2(*reinterpret_cast<const __half2*>(&r8.y));
        float2 f8c = __half22float2(*reinterpret_cast<const __half2*>(&r8.z));
        float2 f8d = __half22float2(*reinterpret_cast<const __half2*>(&r8.w));
        float c8[16];
        c8[0]  = c7[0] * f8a.x; c8[1]  = c7[0] - c8[0];
        c8[2]  = c7[1] * f8a.y; c8[3]  = c7[1] - c8[2];
        c8[4]  = c7[2] * f8b.x; c8[5]  = c7[2] - c8[4];
        c8[6]  = c7[3] * f8b.y; c8[7]  = c7[3] - c8[6];
        c8[8]  = c7[4] * f8c.x; c8[9]  = c7[4] - c8[8];
        c8[10] = c7[5] * f8c.y; c8[11] = c7[5] - c8[10];
        c8[12] = c7[6] * f8d.x; c8[13] = c7[6] - c8[12];
        c8[14] = c7[7] * f8d.y; c8[15] = c7[7] - c8[14];

        // write mu as bf16 pairs over l, in-place into this row (u32 slots s*8..s*8+7)
        unsigned w[8];
#pragma unroll
        for (int jj = 0; jj < 8; jj++) w[jj] = pkf(c8[2 * jj], c8[2 * jj + 1]);
        unsigned* rowbuf = uni + row * 260;
        *reinterpret_cast<uint4*>(rowbuf + s * 8) = *reinterpret_cast<uint4*>(&w[0]);
        *reinterpret_cast<uint4*>(rowbuf + s * 8 + 4) = *reinterpret_cast<uint4*>(&w[4]);
    }
    __syncthreads();

    // ================= phase 4: GEMM3 (mu @ leafp) -> g_part =================
    {
        const unsigned* lpb = g_lp + (size_t)t * (L_ / 2) * 128;

#pragma unroll
        for (int i = 0; i < 2; i++)
#pragma unroll
            for (int j = 0; j < 4; j++)
#pragma unroll
                for (int q = 0; q < 4; q++) acc[i][j][q] = 0.0f;

        auto issue3 = [&](int kt, int buf) {
#pragma unroll
            for (int i = 0; i < 2; i++) {
                int e = tid + i * 256;
                int kp = e >> 5, c4 = e & 31;
                cp16(&Bs0[buf * MS_BS + kp * 132 + c4 * 4],
                     &lpb[(size_t)(kt * 16 + kp) * 128 + c4 * 4]);
            }
            CP_COMMIT();
        };

        issue3(0, 0);
        issue3(1, 1);
#pragma unroll 1
        for (int kt = 0; kt < 16; kt++) {
            const int buf = kt % 3;
            if (kt == 15) { CP_WAIT0(); } else { CP_WAIT1(); }
            __syncthreads();

            const unsigned* Bs = Bs0 + buf * MS_BS;
#pragma unroll
            for (int kh = 0; kh < 2; kh++) {
                const int kbA = kt * 16 + kh * 8;   // A pair base (mu in smem)
                const int kbB = kh * 8;
                unsigned afr[2][4], bfr[4][2];
#pragma unroll
                for (int im = 0; im < 2; im++) {
                    int r = warp_m * 32 + im * 16;
                    afr[im][0] = uni[(r + lq) * 260 + kbA + lr];
                    afr[im][1] = uni[(r + 8 + lq) * 260 + kbA + lr];
                    afr[im][2] = uni[(r + lq) * 260 + kbA + 4 + lr];
                    afr[im][3] = uni[(r + 8 + lq) * 260 + kbA + 4 + lr];
                }
#pragma unroll
                for (int jn = 0; jn < 4; jn++) {
                    int c = warp_n * 32 + jn * 8 + lq;
                    bfr[jn][0] = Bs[(kbB + lr) * 132 + c];
                    bfr[jn][1] = Bs[(kbB + 4 + lr) * 132 + c];
                }
#pragma unroll
                for (int im = 0; im < 2; im++)
#pragma unroll
                    for (int jn = 0; jn < 4; jn++) mma_bf16(acc[im][jn], afr[im], bfr[jn]);
            }
            if (kt + 2 < 16) issue3(kt + 2, (kt + 2) % 3);
        }

        float* pb = g_part + (size_t)t * B_ * C_;
#pragma unroll
        for (int im = 0; im < 2; im++) {
#pragma unroll
            for (int half = 0; half < 2; half++) {
                int r = warp_m * 32 + im * 16 + half * 8 + lq;
#pragma unroll
                for (int jn = 0; jn < 4; jn++) {
                    int c = warp_n * 32 + jn * 8 + lr * 2;
                    if (c >= C_) continue;
                    *reinterpret_cast<float2*>(&pb[(size_t)(b0 + r) * C_ + c]) =
                        make_float2(acc[im][jn][half * 2 + 0], acc[im][jn][half * 2 + 1]);
                }
            }
        }
    }
}

// ---------------------------------------------------------------------------
// Deterministic reduction over trees + final log
// ---------------------------------------------------------------------------
__global__ __launch_bounds__(256) void reduce_log_kernel(float* __restrict__ out) {
    const int i = blockIdx.x * 256 + threadIdx.x;
    float s = 0.0f;
#pragma unroll
    for (int ks = 0; ks < KSPLIT; ks++) s += g_part[(size_t)ks * B_ * C_ + i];
    out[i] = logf(s * (1.0f / (float)(L_ * T_)));
}

extern "C" void kernel_launch(void* const* d_in, const int* in_sizes, int n_in,
                              void* d_out, int out_size) {
    const float* feat = (const float*)d_in[0];
    const float* W1 = (const float*)d_in[1];
    const float* b1 = (const float*)d_in[2];
    const float* W2 = (const float*)d_in[3];
    const float* b2 = (const float*)d_in[4];
    const float* pi = (const float*)d_in[5];
    float* out = (float*)d_out;

    cudaFuncSetAttribute(forest_fused, cudaFuncAttributeMaxDynamicSharedMemorySize, SMEM_BYTES);

    prep_kernel<<<7168, 256>>>(feat, W1, W2, pi);
    forest_fused<<<dim3(B_ / 64, T_), 256, SMEM_BYTES>>>(b1, b2);
    reduce_log_kernel<<<(B_ * C_) / 256, 256>>>(out);
}

// round 12
// speedup vs baseline: 1.1624x; 1.0299x over previous
#include <cuda_runtime.h>
#include <cuda_bf16.h>
#include <cuda_fp16.h>
#include <math.h>

#define T_ 16
#define B_ 1024
#define F_DIM 512
#define H_ 128
#define L_ 512
#define C_ 100
#define KSPLIT 16

// Scratch (static device globals -- no allocation allowed)
__device__ unsigned g_lp[(size_t)T_ * (L_ / 2) * 128];    // 2 MB  packed leafp pairs
__device__ float g_part[(size_t)KSPLIT * B_ * C_];        // 6.5 MB
__device__ unsigned g_pf[(size_t)B_ * (F_DIM / 2)];       // 1 MB  packed feat pairs
__device__ unsigned g_pw1[(size_t)T_ * (F_DIM / 2) * H_]; // 2 MB  packed W1 pairs
__device__ unsigned g_pw2[(size_t)T_ * (H_ / 2) * L_];    // 2 MB  packed W2 pairs

__device__ __forceinline__ unsigned pkf(float lo, float hi) {
    __nv_bfloat162 h = __floats2bfloat162_rn(lo, hi);
    return *reinterpret_cast<unsigned*>(&h);
}

__device__ __forceinline__ void mma_bf16(float* d, const unsigned* a, const unsigned* b) {
    asm volatile(
        "mma.sync.aligned.m16n8k16.row.col.f32.bf16.bf16.f32 "
        "{%0,%1,%2,%3}, {%4,%5,%6,%7}, {%8,%9}, {%0,%1,%2,%3};\n"
        : "+f"(d[0]), "+f"(d[1]), "+f"(d[2]), "+f"(d[3])
        : "r"(a[0]), "r"(a[1]), "r"(a[2]), "r"(a[3]), "r"(b[0]), "r"(b[1]));
}

__device__ __forceinline__ void cp16(void* s, const void* g) {
    unsigned sa = (unsigned)__cvta_generic_to_shared(s);
    asm volatile("cp.async.ca.shared.global [%0], [%1], 16;\n" :: "r"(sa), "l"(g));
}
#define CP_COMMIT() asm volatile("cp.async.commit_group;\n")
#define CP_WAIT1()  asm volatile("cp.async.wait_group 1;\n")
#define CP_WAIT0()  asm volatile("cp.async.wait_group 0;\n")

// ---------------------------------------------------------------------------
// Merged prep, 4 items/thread (MLP>=4):
//   bx [0,256)    : pack feat   (256K u32 items)
//   bx [256,768)  : pack W1     (512K u32 items)
//   bx [768,1280) : pack W2     (512K u32 items)
//   bx [1280,2304): leaf softmax (8 rows/block)
// ---------------------------------------------------------------------------
__global__ __launch_bounds__(256) void prep_kernel(const float* __restrict__ feat,
                                                   const float* __restrict__ W1,
                                                   const float* __restrict__ W2,
                                                   const float* __restrict__ pi) {
    const int bx = blockIdx.x;
    const int tid = threadIdx.x;
    if (bx < 256) {
        // feat: 4 consecutive u32 items = 8 consecutive floats
        const int i = (bx * 256 + tid) * 4;
        float4 a = *reinterpret_cast<const float4*>(&feat[(size_t)i * 2]);
        float4 b = *reinterpret_cast<const float4*>(&feat[(size_t)i * 2 + 4]);
        uint4 u;
        u.x = pkf(a.x, a.y); u.y = pkf(a.z, a.w);
        u.z = pkf(b.x, b.y); u.w = pkf(b.z, b.w);
        *reinterpret_cast<uint4*>(&g_pf[i]) = u;
    } else if (bx < 768) {
        const int i = ((bx - 256) * 256 + tid) * 4;
        int t = i >> 15, rem = i & 32767, f2 = rem >> 7, n = rem & 127;  // n % 4 == 0
        const float* base = W1 + ((size_t)t * F_DIM + 2 * f2) * H_ + n;
        float4 x = *reinterpret_cast<const float4*>(base);
        float4 y = *reinterpret_cast<const float4*>(base + H_);
        uint4 u;
        u.x = pkf(x.x, y.x); u.y = pkf(x.y, y.y);
        u.z = pkf(x.z, y.z); u.w = pkf(x.w, y.w);
        *reinterpret_cast<uint4*>(&g_pw1[i]) = u;
    } else if (bx < 1280) {
        const int i = ((bx - 768) * 256 + tid) * 4;
        int t = i >> 15, h2 = (i >> 9) & 63, l = i & 511;  // l % 4 == 0
        const float* base = W2 + ((size_t)t * H_ + 2 * h2) * L_ + l;
        float4 x = *reinterpret_cast<const float4*>(base);
        float4 y = *reinterpret_cast<const float4*>(base + L_);
        uint4 u;
        u.x = pkf(x.x, y.x); u.y = pkf(x.y, y.y);
        u.z = pkf(x.z, y.z); u.w = pkf(x.w, y.w);
        *reinterpret_cast<uint4*>(&g_pw2[i]) = u;
    } else {
        // softmax: 8 warps/block, one (t,l) row each
        const int row = (bx - 1280) * 8 + (tid >> 5);   // t*L + l
        const int lane = tid & 31;
        const int t = row >> 9, l = row & (L_ - 1);
        const float* pr = pi + (size_t)row * C_;

        float v[4];
#pragma unroll
        for (int j = 0; j < 4; j++) {
            int c = lane + j * 32;
            v[j] = (c < C_) ? pr[c] : -1e30f;
        }
        float m = fmaxf(fmaxf(v[0], v[1]), fmaxf(v[2], v[3]));
#pragma unroll
        for (int o = 16; o; o >>= 1) m = fmaxf(m, __shfl_xor_sync(0xffffffffu, m, o));

        float e[4];
        float s = 0.0f;
#pragma unroll
        for (int j = 0; j < 4; j++) {
            int c = lane + j * 32;
            e[j] = (c < C_) ? __expf(v[j] - m) : 0.0f;
            s += e[j];
        }
#pragma unroll
        for (int o = 16; o; o >>= 1) s += __shfl_xor_sync(0xffffffffu, s, o);
        float inv = 1.0f / s;

        unsigned short* base = reinterpret_cast<unsigned short*>(g_lp);
        const size_t rowbase = ((size_t)t * (L_ / 2) + (l >> 1)) * 128;
#pragma unroll
        for (int j = 0; j < 4; j++) {
            int c = lane + j * 32;
            __nv_bfloat16 bv = __float2bfloat16((c < C_) ? e[j] * inv : 0.0f);
            base[(rowbase + c) * 2 + (l & 1)] = *reinterpret_cast<unsigned short*>(&bv);
        }
    }
}

// ---------------------------------------------------------------------------
// Fully fused per-(tree, 64-row) kernel, 3-stage cp.async, ONE sync per tile:
//   phase1: h  = relu(feat @ W1 + b1)      -> hA (smem, bf16 pairs)
//   phase2: p  = sigmoid(h @ W2 + b2)      -> ph (smem fp16, shifted nodes)
//   phase3: mu = routing products          -> in-place over ph (bf16 pairs)
//   phase4: part[t] = mu @ leafp[t]        -> g_part
// grid (B/64, T) = 256 CTAs, 256 threads, 106.8KB smem (2 CTAs/SM).
// ---------------------------------------------------------------------------
#define MS_HA (64 * 68)
#define MS_BS (16 * 132)
#define MS_AS (64 * 20)
#define PH_U32 (64 * 260)
#define PH_STRIDE 520
#define SMEM_BYTES ((MS_HA + 3 * MS_BS + PH_U32) * 4)

__global__ __launch_bounds__(256, 2) void forest_fused(const float* __restrict__ b1,
                                                       const float* __restrict__ b2) {
    extern __shared__ unsigned sm[];
    unsigned* hA = sm;                          // [64][68]
    unsigned* Bs0 = sm + MS_HA;                 // [3][16*132]
    unsigned* uni = sm + MS_HA + 3 * MS_BS;     // union: As[3][64*20] / ph
    __half* ph = reinterpret_cast<__half*>(uni);

    const int tid = threadIdx.x;
    const int wid = tid >> 5, lane = tid & 31;
    const int warp_m = wid >> 2, warp_n = wid & 3;   // 2x4 warps, 32x32 tiles
    const int lq = lane >> 2, lr = lane & 3;
    const int t = blockIdx.y;
    const int b0 = blockIdx.x * 64;

    float acc[2][4][4];

    // ================= phase 1: GEMM1 -> hA =================
    {
        const unsigned* pf = g_pf + (size_t)b0 * (F_DIM / 2);
        const unsigned* pw = g_pw1 + (size_t)t * (F_DIM / 2) * H_;
        const float* bb = b1 + (size_t)t * H_;

#pragma unroll
        for (int i = 0; i < 2; i++)
#pragma unroll
            for (int j = 0; j < 4; j++)
#pragma unroll
                for (int q = 0; q < 4; q++) acc[i][j][q] = 0.0f;

        auto issue1 = [&](int kt, int buf) {
            const int kp0 = kt * 16;
            {
                int r = tid >> 2, q = tid & 3;
                cp16(&uni[buf * MS_AS + r * 20 + q * 4],
                     &pf[(size_t)r * (F_DIM / 2) + kp0 + q * 4]);
            }
#pragma unroll
            for (int i = 0; i < 2; i++) {
                int e = tid + i * 256;
                int kp = e >> 5, c4 = e & 31;
                cp16(&Bs0[buf * MS_BS + kp * 132 + c4 * 4],
                     &pw[(size_t)(kp0 + kp) * H_ + c4 * 4]);
            }
            CP_COMMIT();
        };

        issue1(0, 0);
        issue1(1, 1);
#pragma unroll 1
        for (int kt = 0; kt < 16; kt++) {
            const int buf = kt % 3;
            if (kt == 15) { CP_WAIT0(); } else { CP_WAIT1(); }
            __syncthreads();

            const unsigned* As = uni + buf * MS_AS;
            const unsigned* Bs = Bs0 + buf * MS_BS;
#pragma unroll
            for (int kh = 0; kh < 2; kh++) {
                const int kb = kh * 8;
                unsigned afr[2][4], bfr[4][2];
#pragma unroll
                for (int im = 0; im < 2; im++) {
                    int r = warp_m * 32 + im * 16;
                    afr[im][0] = As[(r + lq) * 20 + kb + lr];
                    afr[im][1] = As[(r + 8 + lq) * 20 + kb + lr];
                    afr[im][2] = As[(r + lq) * 20 + kb + 4 + lr];
                    afr[im][3] = As[(r + 8 + lq) * 20 + kb + 4 + lr];
                }
#pragma unroll
                for (int jn = 0; jn < 4; jn++) {
                    int c = warp_n * 32 + jn * 8 + lq;
                    bfr[jn][0] = Bs[(kb + lr) * 132 + c];
                    bfr[jn][1] = Bs[(kb + 4 + lr) * 132 + c];
                }
#pragma unroll
                for (int im = 0; im < 2; im++)
#pragma unroll
                    for (int jn = 0; jn < 4; jn++) mma_bf16(acc[im][jn], afr[im], bfr[jn]);
            }
            if (kt + 2 < 16) issue1(kt + 2, (kt + 2) % 3);
        }

        // epilogue -> hA (each warp writes only rows it computed; no cross-warp
        // hazard, and hA is disjoint from As/Bs, so no extra barrier needed)
#pragma unroll
        for (int im = 0; im < 2; im++) {
#pragma unroll
            for (int half = 0; half < 2; half++) {
                int r = warp_m * 32 + im * 16 + half * 8 + lq;
#pragma unroll
                for (int jn = 0; jn < 4; jn++) {
                    int c = warp_n * 32 + jn * 8 + lr * 2;
                    float x0 = fmaxf(acc[im][jn][half * 2 + 0] + bb[c], 0.0f);
                    float x1 = fmaxf(acc[im][jn][half * 2 + 1] + bb[c + 1], 0.0f);
                    hA[r * 68 + (c >> 1)] = pkf(x0, x1);
                }
            }
        }
        __syncthreads();
    }

    // ================= phase 2: GEMM2 + sigmoid -> ph =================
    {
        const unsigned* pw = g_pw2 + (size_t)t * (H_ / 2) * L_;
        const float* bbt = b2 + (size_t)t * L_;

        auto issue2 = [&](int j, int buf) {
            const int chunk = j >> 2, k0s = j & 3;
            const unsigned* src = pw + (size_t)(k0s * 16) * L_ + chunk * 128;
#pragma unroll
            for (int i = 0; i < 2; i++) {
                int e = tid + i * 256;
                int kp = e >> 5, c4 = e & 31;
                cp16(&Bs0[buf * MS_BS + kp * 132 + c4 * 4], &src[(size_t)kp * L_ + c4 * 4]);
            }
            CP_COMMIT();
        };

        issue2(0, 0);
        issue2(1, 1);
#pragma unroll 1
        for (int j = 0; j < 16; j++) {
            const int chunk = j >> 2, k0s = j & 3, buf = j % 3;
            if (k0s == 0) {
#pragma unroll
                for (int i = 0; i < 2; i++)
#pragma unroll
                    for (int jj = 0; jj < 4; jj++)
#pragma unroll
                        for (int q = 0; q < 4; q++) acc[i][jj][q] = 0.0f;
            }
            if (j == 15) { CP_WAIT0(); } else { CP_WAIT1(); }
            __syncthreads();

            const unsigned* Bs = Bs0 + buf * MS_BS;
#pragma unroll
            for (int kh = 0; kh < 2; kh++) {
                const int kbG = k0s * 16 + kh * 8;
                const int kbB = kh * 8;
                unsigned afr[2][4], bfr[4][2];
#pragma unroll
                for (int im = 0; im < 2; im++) {
                    int r = warp_m * 32 + im * 16;
                    afr[im][0] = hA[(r + lq) * 68 + kbG + lr];
                    afr[im][1] = hA[(r + 8 + lq) * 68 + kbG + lr];
                    afr[im][2] = hA[(r + lq) * 68 + kbG + 4 + lr];
                    afr[im][3] = hA[(r + 8 + lq) * 68 + kbG + 4 + lr];
                }
#pragma unroll
                for (int jn = 0; jn < 4; jn++) {
                    int c = warp_n * 32 + jn * 8 + lq;
                    bfr[jn][0] = Bs[(kbB + lr) * 132 + c];
                    bfr[jn][1] = Bs[(kbB + 4 + lr) * 132 + c];
                }
#pragma unroll
                for (int im = 0; im < 2; im++)
#pragma unroll
                    for (int jn = 0; jn < 4; jn++) mma_bf16(acc[im][jn], afr[im], bfr[jn]);
            }

            if (k0s == 3) {
                const int n0c = chunk * 128;
#pragma unroll
                for (int im = 0; im < 2; im++) {
#pragma unroll
                    for (int half = 0; half < 2; half++) {
                        int r = warp_m * 32 + im * 16 + half * 8 + lq;
#pragma unroll
                        for (int jn = 0; jn < 4; jn++) {
                            int c = warp_n * 32 + jn * 8 + lr * 2;
                            float x0 = 1.0f / (1.0f + __expf(-(acc[im][jn][half * 2 + 0] + bbt[n0c + c])));
                            float x1 = 1.0f / (1.0f + __expf(-(acc[im][jn][half * 2 + 1] + bbt[n0c + c + 1])));
                            // shifted node layout: node n -> slot n+1
                            ph[r * PH_STRIDE + 1 + n0c + c] = __float2half(x0);
                            ph[r * PH_STRIDE + 2 + n0c + c] = __float2half(x1);
                        }
                    }
                }
            }
            if (j + 2 < 16) issue2(j + 2, (j + 2) % 3);
        }
        __syncthreads();
    }

    // ================= phase 3: mu in-place over ph =================
#pragma unroll 1
    for (int i = 0; i < 8; i++) {
        int task = i * 256 + tid;
        int row = task >> 5;
        int s = task & 31;
        int l0 = s << 4;
        const __half* sp = ph + row * PH_STRIDE;

        float pref = 1.0f;
#pragma unroll
        for (int d = 0; d < 5; d++) {
            int slot = (1 << d) + (l0 >> (9 - d));
            float v = __half2float(sp[slot]);
            pref *= ((l0 >> (8 - d)) & 1) ? (1.0f - v) : v;
        }

        float v5 = __half2float(sp[32 + s]);
        float c5[2];
        c5[0] = pref * v5;
        c5[1] = pref - c5[0];

        float2 f6 = __half22float2(*reinterpret_cast<const __half2*>(sp + 64 + 2 * s));
        float c6[4];
        c6[0] = c5[0] * f6.x; c6[1] = c5[0] - c6[0];
        c6[2] = c5[1] * f6.y; c6[3] = c5[1] - c6[2];

        uint2 r7 = *reinterpret_cast<const uint2*>(sp + 128 + 4 * s);
        float2 f7a = __half22float2(*reinterpret_cast<const __half2*>(&r7.x));
        float2 f7b = __half22float2(*reinterpret_cast<const __half2*>(&r7.y));
        float c7[8];
        c7[0] = c6[0] * f7a.x; c7[1] = c6[0] - c7[0];
        c7[2] = c6[1] * f7a.y; c7[3] = c6[1] - c7[2];
        c7[4] = c6[2] * f7b.x; c7[5] = c6[2] - c7[4];
        c7[6] = c6[3] * f7b.y; c7[7] = c6[3] - c7[6];

        uint4 r8 = *reinterpret_cast<const uint4*>(sp + 256 + 8 * s);
        float2 f8a = __half22float2(*reinterpret_cast<const __half2*>(&r8.x));
        float2 f8b = __half22float2(*reinterpret_cast<const __half2*>(&r8.y));
        float2 f8c = __half22float2(*reinterpret_cast<const __half2*>(&r8.z));
        float2 f8d = __half22float2(*reinterpret_cast<const __half2*>(&r8.w));
        float c8[16];
        c8[0]  = c7[0] * f8a.x; c8[1]  = c7[0] - c8[0];
        c8[2]  = c7[1] * f8a.y; c8[3]  = c7[1] - c8[2];
        c8[4]  = c7[2] * f8b.x; c8[5]  = c7[2] - c8[4];
        c8[6]  = c7[3] * f8b.y; c8[7]  = c7[3] - c8[6];
        c8[8]  = c7[4] * f8c.x; c8[9]  = c7[4] - c8[8];
        c8[10] = c7[5] * f8c.y; c8[11] = c7[5] - c8[10];
        c8[12] = c7[6] * f8d.x; c8[13] = c7[6] - c8[12];
        c8[14] = c7[7] * f8d.y; c8[15] = c7[7] - c8[14];

        unsigned w[8];
#pragma unroll
        for (int jj = 0; jj < 8; jj++) w[jj] = pkf(c8[2 * jj], c8[2 * jj + 1]);
        unsigned* rowbuf = uni + row * 260;
        *reinterpret_cast<uint4*>(rowbuf + s * 8) = *reinterpret_cast<uint4*>(&w[0]);
        *reinterpret_cast<uint4*>(rowbuf + s * 8 + 4) = *reinterpret_cast<uint4*>(&w[4]);
    }
    __syncthreads();

    // ================= phase 4: GEMM3 (mu @ leafp) -> g_part =================
    {
        const unsigned* lpb = g_lp + (size_t)t * (L_ / 2) * 128;

#pragma unroll
        for (int i = 0; i < 2; i++)
#pragma unroll
            for (int j = 0; j < 4; j++)
#pragma unroll
                for (int q = 0; q < 4; q++) acc[i][j][q] = 0.0f;

        auto issue3 = [&](int kt, int buf) {
#pragma unroll
            for (int i = 0; i < 2; i++) {
                int e = tid + i * 256;
                int kp = e >> 5, c4 = e & 31;
                cp16(&Bs0[buf * MS_BS + kp * 132 + c4 * 4],
                     &lpb[(size_t)(kt * 16 + kp) * 128 + c4 * 4]);
            }
            CP_COMMIT();
        };

        issue3(0, 0);
        issue3(1, 1);
#pragma unroll 1
        for (int kt = 0; kt < 16; kt++) {
            const int buf = kt % 3;
            if (kt == 15) { CP_WAIT0(); } else { CP_WAIT1(); }
            __syncthreads();

            const unsigned* Bs = Bs0 + buf * MS_BS;
#pragma unroll
            for (int kh = 0; kh < 2; kh++) {
                const int kbA = kt * 16 + kh * 8;   // A pair base (mu in smem)
                const int kbB = kh * 8;
                unsigned afr[2][4], bfr[4][2];
#pragma unroll
                for (int im = 0; im < 2; im++) {
                    int r = warp_m * 32 + im * 16;
                    afr[im][0] = uni[(r + lq) * 260 + kbA + lr];
                    afr[im][1] = uni[(r + 8 + lq) * 260 + kbA + lr];
                    afr[im][2] = uni[(r + lq) * 260 + kbA + 4 + lr];
                    afr[im][3] = uni[(r + 8 + lq) * 260 + kbA + 4 + lr];
                }
#pragma unroll
                for (int jn = 0; jn < 4; jn++) {
                    int c = warp_n * 32 + jn * 8 + lq;
                    bfr[jn][0] = Bs[(kbB + lr) * 132 + c];
                    bfr[jn][1] = Bs[(kbB + 4 + lr) * 132 + c];
                }
#pragma unroll
                for (int im = 0; im < 2; im++)
#pragma unroll
                    for (int jn = 0; jn < 4; jn++) mma_bf16(acc[im][jn], afr[im], bfr[jn]);
            }
            if (kt + 2 < 16) issue3(kt + 2, (kt + 2) % 3);
        }

        float* pb = g_part + (size_t)t * B_ * C_;
#pragma unroll
        for (int im = 0; im < 2; im++) {
#pragma unroll
            for (int half = 0; half < 2; half++) {
                int r = warp_m * 32 + im * 16 + half * 8 + lq;
#pragma unroll
                for (int jn = 0; jn < 4; jn++) {
                    int c = warp_n * 32 + jn * 8 + lr * 2;
                    if (c >= C_) continue;
                    *reinterpret_cast<float2*>(&pb[(size_t)(b0 + r) * C_ + c]) =
                        make_float2(acc[im][jn][half * 2 + 0], acc[im][jn][half * 2 + 1]);
                }
            }
        }
    }
}

// ---------------------------------------------------------------------------
// Deterministic reduction over trees + final log, float4-vectorized.
// 25600 threads, each: 16 independent LDG.128 (one per tree), 1 STG.128.
// ---------------------------------------------------------------------------
__global__ __launch_bounds__(256) void reduce_log_kernel(float* __restrict__ out) {
    const int c = (blockIdx.x * 256 + threadIdx.x) * 4;   // 0 .. B*C-4
    float4 s = make_float4(0.f, 0.f, 0.f, 0.f);
#pragma unroll
    for (int ks = 0; ks < KSPLIT; ks++) {
        float4 v = *reinterpret_cast<const float4*>(&g_part[(size_t)ks * B_ * C_ + c]);
        s.x += v.x; s.y += v.y; s.z += v.z; s.w += v.w;
    }
    const float sc = 1.0f / (float)(L_ * T_);
    float4 r;
    r.x = logf(s.x * sc); r.y = logf(s.y * sc);
    r.z = logf(s.z * sc); r.w = logf(s.w * sc);
    *reinterpret_cast<float4*>(&out[c]) = r;
}

extern "C" void kernel_launch(void* const* d_in, const int* in_sizes, int n_in,
                              void* d_out, int out_size) {
    const float* feat = (const float*)d_in[0];
    const float* W1 = (const float*)d_in[1];
    const float* b1 = (const float*)d_in[2];
    const float* W2 = (const float*)d_in[3];
    const float* b2 = (const float*)d_in[4];
    const float* pi = (const float*)d_in[5];
    float* out = (float*)d_out;

    cudaFuncSetAttribute(forest_fused, cudaFuncAttributeMaxDynamicSharedMemorySize, SMEM_BYTES);

    prep_kernel<<<2304, 256>>>(feat, W1, W2, pi);
    forest_fused<<<dim3(B_ / 64, T_), 256, SMEM_BYTES>>>(b1, b2);
    reduce_log_kernel<<<(B_ * C_) / 1024, 256>>>(out);
}

// round 13
// speedup vs baseline: 1.2420x; 1.0685x over previous
#include <cuda_runtime.h>
#include <cuda_bf16.h>
#include <cuda_fp16.h>
#include <math.h>

#define T_ 16
#define B_ 1024
#define F_DIM 512
#define H_ 128
#define L_ 512
#define C_ 100
#define KSPLIT 16

// Scratch (static device globals -- no allocation allowed)
__device__ unsigned g_lp[(size_t)T_ * (L_ / 2) * 128];    // 2 MB  packed leafp pairs
__device__ float g_part[(size_t)KSPLIT * B_ * C_];        // 6.5 MB
__device__ unsigned g_pf[(size_t)B_ * (F_DIM / 2)];       // 1 MB  packed feat pairs
__device__ unsigned g_pw1[(size_t)T_ * (F_DIM / 2) * H_]; // 2 MB  packed W1 pairs
__device__ unsigned g_pw2[(size_t)T_ * (H_ / 2) * L_];    // 2 MB  packed W2 pairs

__device__ __forceinline__ unsigned pkf(float lo, float hi) {
    __nv_bfloat162 h = __floats2bfloat162_rn(lo, hi);
    return *reinterpret_cast<unsigned*>(&h);
}

__device__ __forceinline__ void mma_bf16(float* d, const unsigned* a, const unsigned* b) {
    asm volatile(
        "mma.sync.aligned.m16n8k16.row.col.f32.bf16.bf16.f32 "
        "{%0,%1,%2,%3}, {%4,%5,%6,%7}, {%8,%9}, {%0,%1,%2,%3};\n"
        : "+f"(d[0]), "+f"(d[1]), "+f"(d[2]), "+f"(d[3])
        : "r"(a[0]), "r"(a[1]), "r"(a[2]), "r"(a[3]), "r"(b[0]), "r"(b[1]));
}

__device__ __forceinline__ void cp16(void* s, const void* g) {
    unsigned sa = (unsigned)__cvta_generic_to_shared(s);
    asm volatile("cp.async.ca.shared.global [%0], [%1], 16;\n" :: "r"(sa), "l"(g));
}
#define CP_COMMIT() asm volatile("cp.async.commit_group;\n")
#define CP_WAIT1()  asm volatile("cp.async.wait_group 1;\n")
#define CP_WAIT0()  asm volatile("cp.async.wait_group 0;\n")

// ---------------------------------------------------------------------------
// Merged prep, 8 u32 items/thread (4 independent LDG.128, MLP>=4):
//   bx [0,128)    : pack feat   (256K items)
//   bx [128,384)  : pack W1     (512K items)
//   bx [384,640)  : pack W2     (512K items)
//   bx [640,1664) : leaf softmax (8 rows/block)
// ---------------------------------------------------------------------------
__global__ __launch_bounds__(256) void prep_kernel(const float* __restrict__ feat,
                                                   const float* __restrict__ W1,
                                                   const float* __restrict__ W2,
                                                   const float* __restrict__ pi) {
    const int bx = blockIdx.x;
    const int tid = threadIdx.x;
    if (bx < 128) {
        const int i = (bx * 256 + tid) * 8;     // 8 u32 items = 16 floats
        float4 a = *reinterpret_cast<const float4*>(&feat[(size_t)i * 2]);
        float4 b = *reinterpret_cast<const float4*>(&feat[(size_t)i * 2 + 4]);
        float4 cc = *reinterpret_cast<const float4*>(&feat[(size_t)i * 2 + 8]);
        float4 d = *reinterpret_cast<const float4*>(&feat[(size_t)i * 2 + 12]);
        uint4 u0, u1;
        u0.x = pkf(a.x, a.y); u0.y = pkf(a.z, a.w);
        u0.z = pkf(b.x, b.y); u0.w = pkf(b.z, b.w);
        u1.x = pkf(cc.x, cc.y); u1.y = pkf(cc.z, cc.w);
        u1.z = pkf(d.x, d.y); u1.w = pkf(d.z, d.w);
        *reinterpret_cast<uint4*>(&g_pf[i]) = u0;
        *reinterpret_cast<uint4*>(&g_pf[i + 4]) = u1;
    } else if (bx < 384) {
        const int i = ((bx - 128) * 256 + tid) * 8;
        int t = i >> 15, rem = i & 32767, f2 = rem >> 7, n = rem & 127;  // n % 8 == 0
        const float* base = W1 + ((size_t)t * F_DIM + 2 * f2) * H_ + n;
        float4 x0 = *reinterpret_cast<const float4*>(base);
        float4 x1 = *reinterpret_cast<const float4*>(base + 4);
        float4 y0 = *reinterpret_cast<const float4*>(base + H_);
        float4 y1 = *reinterpret_cast<const float4*>(base + H_ + 4);
        uint4 u0, u1;
        u0.x = pkf(x0.x, y0.x); u0.y = pkf(x0.y, y0.y);
        u0.z = pkf(x0.z, y0.z); u0.w = pkf(x0.w, y0.w);
        u1.x = pkf(x1.x, y1.x); u1.y = pkf(x1.y, y1.y);
        u1.z = pkf(x1.z, y1.z); u1.w = pkf(x1.w, y1.w);
        *reinterpret_cast<uint4*>(&g_pw1[i]) = u0;
        *reinterpret_cast<uint4*>(&g_pw1[i + 4]) = u1;
    } else if (bx < 640) {
        const int i = ((bx - 384) * 256 + tid) * 8;
        int t = i >> 15, h2 = (i >> 9) & 63, l = i & 511;  // l % 8 == 0
        const float* base = W2 + ((size_t)t * H_ + 2 * h2) * L_ + l;
        float4 x0 = *reinterpret_cast<const float4*>(base);
        float4 x1 = *reinterpret_cast<const float4*>(base + 4);
        float4 y0 = *reinterpret_cast<const float4*>(base + L_);
        float4 y1 = *reinterpret_cast<const float4*>(base + L_ + 4);
        uint4 u0, u1;
        u0.x = pkf(x0.x, y0.x); u0.y = pkf(x0.y, y0.y);
        u0.z = pkf(x0.z, y0.z); u0.w = pkf(x0.w, y0.w);
        u1.x = pkf(x1.x, y1.x); u1.y = pkf(x1.y, y1.y);
        u1.z = pkf(x1.z, y1.z); u1.w = pkf(x1.w, y1.w);
        *reinterpret_cast<uint4*>(&g_pw2[i]) = u0;
        *reinterpret_cast<uint4*>(&g_pw2[i + 4]) = u1;
    } else {
        // softmax: 8 warps/block, one (t,l) row each
        const int row = (bx - 640) * 8 + (tid >> 5);   // t*L + l
        const int lane = tid & 31;
        const int t = row >> 9, l = row & (L_ - 1);
        const float* pr = pi + (size_t)row * C_;

        float v[4];
#pragma unroll
        for (int j = 0; j < 4; j++) {
            int c = lane + j * 32;
            v[j] = (c < C_) ? pr[c] : -1e30f;
        }
        float m = fmaxf(fmaxf(v[0], v[1]), fmaxf(v[2], v[3]));
#pragma unroll
        for (int o = 16; o; o >>= 1) m = fmaxf(m, __shfl_xor_sync(0xffffffffu, m, o));

        float e[4];
        float s = 0.0f;
#pragma unroll
        for (int j = 0; j < 4; j++) {
            int c = lane + j * 32;
            e[j] = (c < C_) ? __expf(v[j] - m) : 0.0f;
            s += e[j];
        }
#pragma unroll
        for (int o = 16; o; o >>= 1) s += __shfl_xor_sync(0xffffffffu, s, o);
        float inv = 1.0f / s;

        unsigned short* base = reinterpret_cast<unsigned short*>(g_lp);
        const size_t rowbase = ((size_t)t * (L_ / 2) + (l >> 1)) * 128;
#pragma unroll
        for (int j = 0; j < 4; j++) {
            int c = lane + j * 32;
            __nv_bfloat16 bv = __float2bfloat16((c < C_) ? e[j] * inv : 0.0f);
            base[(rowbase + c) * 2 + (l & 1)] = *reinterpret_cast<unsigned short*>(&bv);
        }
    }
}

// ---------------------------------------------------------------------------
// Fully fused per-(tree, 64-row) kernel, 3-stage cp.async, ONE sync per tile.
// Bs stride 136 (mod 32 = 8 -> banks 8*lr+lq, all 32 distinct: conflict-free).
// grid (B/64, T) = 256 CTAs, 256 threads, 107.5KB smem (2 CTAs/SM).
// ---------------------------------------------------------------------------
#define MS_HA (64 * 68)
#define MS_BS (16 * 136)
#define MS_AS (64 * 20)
#define PH_U32 (64 * 260)
#define PH_STRIDE 520
#define SMEM_BYTES ((MS_HA + 3 * MS_BS + PH_U32) * 4)

__global__ __launch_bounds__(256, 2) void forest_fused(const float* __restrict__ b1,
                                                       const float* __restrict__ b2) {
    extern __shared__ unsigned sm[];
    unsigned* hA = sm;                          // [64][68]
    unsigned* Bs0 = sm + MS_HA;                 // [3][16*136]
    unsigned* uni = sm + MS_HA + 3 * MS_BS;     // union: As[3][64*20] / ph
    __half* ph = reinterpret_cast<__half*>(uni);

    const int tid = threadIdx.x;
    const int wid = tid >> 5, lane = tid & 31;
    const int warp_m = wid >> 2, warp_n = wid & 3;   // 2x4 warps, 32x32 tiles
    const int lq = lane >> 2, lr = lane & 3;
    const int t = blockIdx.y;
    const int b0 = blockIdx.x * 64;

    float acc[2][4][4];

    // ================= phase 1: GEMM1 -> hA =================
    {
        const unsigned* pf = g_pf + (size_t)b0 * (F_DIM / 2);
        const unsigned* pw = g_pw1 + (size_t)t * (F_DIM / 2) * H_;
        const float* bb = b1 + (size_t)t * H_;

#pragma unroll
        for (int i = 0; i < 2; i++)
#pragma unroll
            for (int j = 0; j < 4; j++)
#pragma unroll
                for (int q = 0; q < 4; q++) acc[i][j][q] = 0.0f;

        auto issue1 = [&](int kt, int buf) {
            const int kp0 = kt * 16;
            {
                int r = tid >> 2, q = tid & 3;
                cp16(&uni[buf * MS_AS + r * 20 + q * 4],
                     &pf[(size_t)r * (F_DIM / 2) + kp0 + q * 4]);
            }
#pragma unroll
            for (int i = 0; i < 2; i++) {
                int e = tid + i * 256;
                int kp = e >> 5, c4 = e & 31;
                cp16(&Bs0[buf * MS_BS + kp * 136 + c4 * 4],
                     &pw[(size_t)(kp0 + kp) * H_ + c4 * 4]);
            }
            CP_COMMIT();
        };

        issue1(0, 0);
        issue1(1, 1);
#pragma unroll 1
        for (int kt = 0; kt < 16; kt++) {
            const int buf = kt % 3;
            if (kt == 15) { CP_WAIT0(); } else { CP_WAIT1(); }
            __syncthreads();

            const unsigned* As = uni + buf * MS_AS;
            const unsigned* Bs = Bs0 + buf * MS_BS;
#pragma unroll
            for (int kh = 0; kh < 2; kh++) {
                const int kb = kh * 8;
                unsigned afr[2][4], bfr[4][2];
#pragma unroll
                for (int im = 0; im < 2; im++) {
                    int r = warp_m * 32 + im * 16;
                    afr[im][0] = As[(r + lq) * 20 + kb + lr];
                    afr[im][1] = As[(r + 8 + lq) * 20 + kb + lr];
                    afr[im][2] = As[(r + lq) * 20 + kb + 4 + lr];
                    afr[im][3] = As[(r + 8 + lq) * 20 + kb + 4 + lr];
                }
#pragma unroll
                for (int jn = 0; jn < 4; jn++) {
                    int c = warp_n * 32 + jn * 8 + lq;
                    bfr[jn][0] = Bs[(kb + lr) * 136 + c];
                    bfr[jn][1] = Bs[(kb + 4 + lr) * 136 + c];
                }
#pragma unroll
                for (int im = 0; im < 2; im++)
#pragma unroll
                    for (int jn = 0; jn < 4; jn++) mma_bf16(acc[im][jn], afr[im], bfr[jn]);
            }
            if (kt + 2 < 16) issue1(kt + 2, (kt + 2) % 3);
        }

        // epilogue -> hA (warp-private rows, disjoint region: no barrier needed)
#pragma unroll
        for (int im = 0; im < 2; im++) {
#pragma unroll
            for (int half = 0; half < 2; half++) {
                int r = warp_m * 32 + im * 16 + half * 8 + lq;
#pragma unroll
                for (int jn = 0; jn < 4; jn++) {
                    int c = warp_n * 32 + jn * 8 + lr * 2;
                    float x0 = fmaxf(acc[im][jn][half * 2 + 0] + bb[c], 0.0f);
                    float x1 = fmaxf(acc[im][jn][half * 2 + 1] + bb[c + 1], 0.0f);
                    hA[r * 68 + (c >> 1)] = pkf(x0, x1);
                }
            }
        }
        __syncthreads();
    }

    // ================= phase 2: GEMM2 + sigmoid -> ph =================
    {
        const unsigned* pw = g_pw2 + (size_t)t * (H_ / 2) * L_;
        const float* bbt = b2 + (size_t)t * L_;

        auto issue2 = [&](int j, int buf) {
            const int chunk = j >> 2, k0s = j & 3;
            const unsigned* src = pw + (size_t)(k0s * 16) * L_ + chunk * 128;
#pragma unroll
            for (int i = 0; i < 2; i++) {
                int e = tid + i * 256;
                int kp = e >> 5, c4 = e & 31;
                cp16(&Bs0[buf * MS_BS + kp * 136 + c4 * 4], &src[(size_t)kp * L_ + c4 * 4]);
            }
            CP_COMMIT();
        };

        issue2(0, 0);
        issue2(1, 1);
#pragma unroll 1
        for (int j = 0; j < 16; j++) {
            const int chunk = j >> 2, k0s = j & 3, buf = j % 3;
            if (k0s == 0) {
#pragma unroll
                for (int i = 0; i < 2; i++)
#pragma unroll
                    for (int jj = 0; jj < 4; jj++)
#pragma unroll
                        for (int q = 0; q < 4; q++) acc[i][jj][q] = 0.0f;
            }
            if (j == 15) { CP_WAIT0(); } else { CP_WAIT1(); }
            __syncthreads();

            const unsigned* Bs = Bs0 + buf * MS_BS;
#pragma unroll
            for (int kh = 0; kh < 2; kh++) {
                const int kbG = k0s * 16 + kh * 8;
                const int kbB = kh * 8;
                unsigned afr[2][4], bfr[4][2];
#pragma unroll
                for (int im = 0; im < 2; im++) {
                    int r = warp_m * 32 + im * 16;
                    afr[im][0] = hA[(r + lq) * 68 + kbG + lr];
                    afr[im][1] = hA[(r + 8 + lq) * 68 + kbG + lr];
                    afr[im][2] = hA[(r + lq) * 68 + kbG + 4 + lr];
                    afr[im][3] = hA[(r + 8 + lq) * 68 + kbG + 4 + lr];
                }
#pragma unroll
                for (int jn = 0; jn < 4; jn++) {
                    int c = warp_n * 32 + jn * 8 + lq;
                    bfr[jn][0] = Bs[(kbB + lr) * 136 + c];
                    bfr[jn][1] = Bs[(kbB + 4 + lr) * 136 + c];
                }
#pragma unroll
                for (int im = 0; im < 2; im++)
#pragma unroll
                    for (int jn = 0; jn < 4; jn++) mma_bf16(acc[im][jn], afr[im], bfr[jn]);
            }

            if (k0s == 3) {
                const int n0c = chunk * 128;
#pragma unroll
                for (int im = 0; im < 2; im++) {
#pragma unroll
                    for (int half = 0; half < 2; half++) {
                        int r = warp_m * 32 + im * 16 + half * 8 + lq;
#pragma unroll
                        for (int jn = 0; jn < 4; jn++) {
                            int c = warp_n * 32 + jn * 8 + lr * 2;
                            float x0 = 1.0f / (1.0f + __expf(-(acc[im][jn][half * 2 + 0] + bbt[n0c + c])));
                            float x1 = 1.0f / (1.0f + __expf(-(acc[im][jn][half * 2 + 1] + bbt[n0c + c + 1])));
                            // shifted node layout: node n -> slot n+1
                            ph[r * PH_STRIDE + 1 + n0c + c] = __float2half(x0);
                            ph[r * PH_STRIDE + 2 + n0c + c] = __float2half(x1);
                        }
                    }
                }
            }
            if (j + 2 < 16) issue2(j + 2, (j + 2) % 3);
        }
        __syncthreads();
    }

    // ================= phase 3: mu in-place over ph =================
#pragma unroll 1
    for (int i = 0; i < 8; i++) {
        int task = i * 256 + tid;
        int row = task >> 5;
        int s = task & 31;
        int l0 = s << 4;
        const __half* sp = ph + row * PH_STRIDE;

        float pref = 1.0f;
#pragma unroll
        for (int d = 0; d < 5; d++) {
            int slot = (1 << d) + (l0 >> (9 - d));
            float v = __half2float(sp[slot]);
            pref *= ((l0 >> (8 - d)) & 1) ? (1.0f - v) : v;
        }

        float v5 = __half2float(sp[32 + s]);
        float c5[2];
        c5[0] = pref * v5;
        c5[1] = pref - c5[0];

        float2 f6 = __half22float2(*reinterpret_cast<const __half2*>(sp + 64 + 2 * s));
        float c6[4];
        c6[0] = c5[0] * f6.x; c6[1] = c5[0] - c6[0];
        c6[2] = c5[1] * f6.y; c6[3] = c5[1] - c6[2];

        uint2 r7 = *reinterpret_cast<const uint2*>(sp + 128 + 4 * s);
        float2 f7a = __half22float2(*reinterpret_cast<const __half2*>(&r7.x));
        float2 f7b = __half22float2(*reinterpret_cast<const __half2*>(&r7.y));
        float c7[8];
        c7[0] = c6[0] * f7a.x; c7[1] = c6[0] - c7[0];
        c7[2] = c6[1] * f7a.y; c7[3] = c6[1] - c7[2];
        c7[4] = c6[2] * f7b.x; c7[5] = c6[2] - c7[4];
        c7[6] = c6[3] * f7b.y; c7[7] = c6[3] - c7[6];

        uint4 r8 = *reinterpret_cast<const uint4*>(sp + 256 + 8 * s);
        float2 f8a = __half22float2(*reinterpret_cast<const __half2*>(&r8.x));
        float2 f8b = __half22float2(*reinterpret_cast<const __half2*>(&r8.y));
        float2 f8c = __half22float2(*reinterpret_cast<const __half2*>(&r8.z));
        float2 f8d = __half22float2(*reinterpret_cast<const __half2*>(&r8.w));
        float c8[16];
        c8[0]  = c7[0] * f8a.x; c8[1]  = c7[0] - c8[0];
        c8[2]  = c7[1] * f8a.y; c8[3]  = c7[1] - c8[2];
        c8[4]  = c7[2] * f8b.x; c8[5]  = c7[2] - c8[4];
        c8[6]  = c7[3] * f8b.y; c8[7]  = c7[3] - c8[6];
        c8[8]  = c7[4] * f8c.x; c8[9]  = c7[4] - c8[8];
        c8[10] = c7[5] * f8c.y; c8[11] = c7[5] - c8[10];
        c8[12] = c7[6] * f8d.x; c8[13] = c7[6] - c8[12];
        c8[14] = c7[7] * f8d.y; c8[15] = c7[7] - c8[14];

        unsigned w[8];
#pragma unroll
        for (int jj = 0; jj < 8; jj++) w[jj] = pkf(c8[2 * jj], c8[2 * jj + 1]);
        unsigned* rowbuf = uni + row * 260;
        *reinterpret_cast<uint4*>(rowbuf + s * 8) = *reinterpret_cast<uint4*>(&w[0]);
        *reinterpret_cast<uint4*>(rowbuf + s * 8 + 4) = *reinterpret_cast<uint4*>(&w[4]);
    }
    __syncthreads();

    // ================= phase 4: GEMM3 (mu @ leafp) -> g_part =================
    {
        const unsigned* lpb = g_lp + (size_t)t * (L_ / 2) * 128;

#pragma unroll
        for (int i = 0; i < 2; i++)
#pragma unroll
            for (int j = 0; j < 4; j++)
#pragma unroll
                for (int q = 0; q < 4; q++) acc[i][j][q] = 0.0f;

        auto issue3 = [&](int kt, int buf) {
#pragma unroll
            for (int i = 0; i < 2; i++) {
                int e = tid + i * 256;
                int kp = e >> 5, c4 = e & 31;
                cp16(&Bs0[buf * MS_BS + kp * 136 + c4 * 4],
                     &lpb[(size_t)(kt * 16 + kp) * 128 + c4 * 4]);
            }
            CP_COMMIT();
        };

        issue3(0, 0);
        issue3(1, 1);
#pragma unroll 1
        for (int kt = 0; kt < 16; kt++) {
            const int buf = kt % 3;
            if (kt == 15) { CP_WAIT0(); } else { CP_WAIT1(); }
            __syncthreads();

            const unsigned* Bs = Bs0 + buf * MS_BS;
#pragma unroll
            for (int kh = 0; kh < 2; kh++) {
                const int kbA = kt * 16 + kh * 8;   // A pair base (mu in smem)
                const int kbB = kh * 8;
                unsigned afr[2][4], bfr[4][2];
#pragma unroll
                for (int im = 0; im < 2; im++) {
                    int r = warp_m * 32 + im * 16;
                    afr[im][0] = uni[(r + lq) * 260 + kbA + lr];
                    afr[im][1] = uni[(r + 8 + lq) * 260 + kbA + lr];
                    afr[im][2] = uni[(r + lq) * 260 + kbA + 4 + lr];
                    afr[im][3] = uni[(r + 8 + lq) * 260 + kbA + 4 + lr];
                }
#pragma unroll
                for (int jn = 0; jn < 4; jn++) {
                    int c = warp_n * 32 + jn * 8 + lq;
                    bfr[jn][0] = Bs[(kbB + lr) * 136 + c];
                    bfr[jn][1] = Bs[(kbB + 4 + lr) * 136 + c];
                }
#pragma unroll
                for (int im = 0; im < 2; im++)
#pragma unroll
                    for (int jn = 0; jn < 4; jn++) mma_bf16(acc[im][jn], afr[im], bfr[jn]);
            }
            if (kt + 2 < 16) issue3(kt + 2, (kt + 2) % 3);
        }

        float* pb = g_part + (size_t)t * B_ * C_;
#pragma unroll
        for (int im = 0; im < 2; im++) {
#pragma unroll
            for (int half = 0; half < 2; half++) {
                int r = warp_m * 32 + im * 16 + half * 8 + lq;
#pragma unroll
                for (int jn = 0; jn < 4; jn++) {
                    int c = warp_n * 32 + jn * 8 + lr * 2;
                    if (c >= C_) continue;
                    *reinterpret_cast<float2*>(&pb[(size_t)(b0 + r) * C_ + c]) =
                        make_float2(acc[im][jn][half * 2 + 0], acc[im][jn][half * 2 + 1]);
                }
            }
        }
    }
}

// ---------------------------------------------------------------------------
// Deterministic reduction over trees + final log, float4-vectorized.
// ---------------------------------------------------------------------------
__global__ __launch_bounds__(256) void reduce_log_kernel(float* __restrict__ out) {
    const int c = (blockIdx.x * 256 + threadIdx.x) * 4;   // 0 .. B*C-4
    float4 s = make_float4(0.f, 0.f, 0.f, 0.f);
#pragma unroll
    for (int ks = 0; ks < KSPLIT; ks++) {
        float4 v = *reinterpret_cast<const float4*>(&g_part[(size_t)ks * B_ * C_ + c]);
        s.x += v.x; s.y += v.y; s.z += v.z; s.w += v.w;
    }
    const float sc = 1.0f / (float)(L_ * T_);
    float4 r;
    r.x = logf(s.x * sc); r.y = logf(s.y * sc);
    r.z = logf(s.z * sc); r.w = logf(s.w * sc);
    *reinterpret_cast<float4*>(&out[c]) = r;
}

extern "C" void kernel_launch(void* const* d_in, const int* in_sizes, int n_in,
                              void* d_out, int out_size) {
    const float* feat = (const float*)d_in[0];
    const float* W1 = (const float*)d_in[1];
    const float* b1 = (const float*)d_in[2];
    const float* W2 = (const float*)d_in[3];
    const float* b2 = (const float*)d_in[4];
    const float* pi = (const float*)d_in[5];
    float* out = (float*)d_out;

    cudaFuncSetAttribute(forest_fused, cudaFuncAttributeMaxDynamicSharedMemorySize, SMEM_BYTES);

    prep_kernel<<<1664, 256>>>(feat, W1, W2, pi);
    forest_fused<<<dim3(B_ / 64, T_), 256, SMEM_BYTES>>>(b1, b2);
    reduce_log_kernel<<<(B_ * C_) / 1024, 256>>>(out);
}